// round 14
// baseline (speedup 1.0000x reference)
#include <cuda_runtime.h>
#include <cuda_fp16.h>
#include <cstdint>

#define NB 256
#define NS 32
#define NV 10000
#define DEMB 512
#define DHID 1024
#define DIMG 2048
#define BOS_TOK 1
#define EOS_TOK 2

// B-plane pre-scale (exact power of two) to keep fp16 low-split out of subnormals
#define BSCALE 256.0f
#define INVBSC 0.00390625f

// ---------------- device scratch (static, no allocations) ----------------
__device__ float g_h0[NB * DHID];
__device__ float g_h1[NB * DHID];
__device__ float g_G1[NB * 3 * DHID];
__device__ float g_G2[NB * 3 * DHID];
__device__ unsigned long long g_amax[NB];
__device__ int g_tok[NS * NB];

// fp16 2-split planes (plane p at offset p*planeElems). Weights scaled by BSCALE.
__device__ uint16_t g_pImg [2u * NB * DIMG];
__device__ uint16_t g_pWbT [2u * DHID * DIMG];
__device__ uint16_t g_pWih [2u * 3 * DHID * DEMB];
__device__ uint16_t g_pWhh [2u * 3 * DHID * DHID];
__device__ uint16_t g_pWout[2u * NV * DHID];
__device__ uint16_t g_pX   [2u * NB * DEMB];
__device__ uint16_t g_pHA  [2u * NB * DHID];
__device__ uint16_t g_pHB  [2u * NB * DHID];

// order-preserving (float,index) pack; max => max value, ties => smallest index
__device__ __forceinline__ unsigned long long packmax(float v, int idx) {
    unsigned int b = __float_as_uint(v);
    b = (b & 0x80000000u) ? ~b : (b | 0x80000000u);
    return ((unsigned long long)b << 32) | (unsigned long long)(0xFFFFFFFFu - (unsigned)idx);
}

// ---------------- fp16 2-way split helpers ----------------
__device__ __forceinline__ uint32_t packh2(float hi, float lo) {
    uint32_t r;
    asm("cvt.rn.f16x2.f32 %0, %1, %2;" : "=r"(r) : "f"(hi), "f"(lo));
    return r;
}
__device__ __forceinline__ void split2(float x0, float x1, uint32_t& w0, uint32_t& w1) {
    w0 = packh2(x1, x0);
    __half2 h2 = *reinterpret_cast<const __half2*>(&w0);
    float r0 = x0 - __low2float(h2);
    float r1 = x1 - __high2float(h2);
    w1 = packh2(r1, r0);
}

// ---------------- mma / ldmatrix / cp.async ----------------
__device__ __forceinline__ void mma_f16(float4& d, const uint32_t* a, const uint32_t* b) {
    asm volatile(
        "mma.sync.aligned.m16n8k16.row.col.f32.f16.f16.f32 "
        "{%0,%1,%2,%3}, {%4,%5,%6,%7}, {%8,%9}, {%0,%1,%2,%3};"
        : "+f"(d.x), "+f"(d.y), "+f"(d.z), "+f"(d.w)
        : "r"(a[0]), "r"(a[1]), "r"(a[2]), "r"(a[3]), "r"(b[0]), "r"(b[1]));
}
__device__ __forceinline__ void ldsm4(uint32_t& r0, uint32_t& r1, uint32_t& r2, uint32_t& r3,
                                      unsigned addr) {
    asm volatile("ldmatrix.sync.aligned.m8n8.x4.shared.b16 {%0,%1,%2,%3}, [%4];"
                 : "=r"(r0), "=r"(r1), "=r"(r2), "=r"(r3) : "r"(addr));
}
__device__ __forceinline__ void cpa16(unsigned dst, const void* src, unsigned srcsz) {
    asm volatile("cp.async.cg.shared.global [%0], [%1], 16, %2;"
                 :: "r"(dst), "l"(src), "r"(srcsz));
}
__device__ __forceinline__ void cpa_commit() {
    asm volatile("cp.async.commit_group;" ::: "memory");
}
__device__ __forceinline__ void cpa_wait0() {
    asm volatile("cp.async.wait_group 0;" ::: "memory");
}

// ---------------- one-time: split a matrix into 2 fp16 planes (optional scale) ----------------
__global__ void split_mat(const float* __restrict__ src, uint16_t* __restrict__ dst, long n2, float sc) {
    long i = (long)blockIdx.x * blockDim.x + threadIdx.x;
    if (i >= n2) return;
    float2 v = ((const float2*)src)[i];
    uint32_t w0, w1;
    split2(v.x * sc, v.y * sc, w0, w1);
    uint32_t* d = (uint32_t*)dst;
    d[i] = w0; d[i + n2] = w1;
}

// ---------------- one-time: W_b transpose + split (scaled) ----------------
__global__ void transpose_split_wb(const float* __restrict__ Wb) {
    __shared__ float t[32][33];
    int k0 = blockIdx.x * 32;
    int n0 = blockIdx.y * 32;
    for (int i = threadIdx.y; i < 32; i += 8)
        t[i][threadIdx.x] = Wb[(size_t)(k0 + i) * DHID + n0 + threadIdx.x];
    __syncthreads();
    const size_t PS = (size_t)DHID * DIMG;
    for (int i = threadIdx.y; i < 32; i += 8) {
        float v = t[threadIdx.x][i] * BSCALE;
        uint32_t w0, w1;
        split2(v, 0.f, w0, w1);
        size_t o = (size_t)(n0 + i) * DIMG + k0 + threadIdx.x;
        g_pWbT[o]      = (uint16_t)(w0 & 0xFFFF);
        g_pWbT[o + PS] = (uint16_t)(w1 & 0xFFFF);
    }
}

// ---------------- zero the one-hot output ----------------
__global__ void zero_out(float4* o, long long n4) {
    long long i = (long long)blockIdx.x * blockDim.x + threadIdx.x;
    if (i < n4) o[i] = make_float4(0.f, 0.f, 0.f, 0.f);
}

// ---------------- write relu(emb[token]) into g_pX planes (one row, 128 threads) ----------------
__device__ __forceinline__ void write_x_planes(const float* __restrict__ emb, int tok, int b, int tid) {
    const int k = tid * 4;
    float4 e = *(const float4*)(emb + (size_t)tok * DEMB + k);
    e.x = fmaxf(e.x, 0.f); e.y = fmaxf(e.y, 0.f);
    e.z = fmaxf(e.z, 0.f); e.w = fmaxf(e.w, 0.f);
    uint32_t a0, a1, b0, b1;
    split2(e.x, e.y, a0, a1);
    split2(e.z, e.w, b0, b1);
    const long PS = (long)NB * DEMB / 2;
    uint32_t* d = (uint32_t*)g_pX;
    long o = ((long)b * DEMB + k) >> 1;
    d[o] = a0;      d[o + 1] = b0;
    d[o + PS] = a1; d[o + 1 + PS] = b1;
}

// ---------------- init: x0 planes = relu(emb[BOS]), amax reset ----------------
__global__ void init_kernel(const float* __restrict__ emb) {
    int b = blockIdx.x;
    if (threadIdx.x == 0) g_amax[b] = 0ull;
    write_x_planes(emb, BOS_TOK, b, threadIdx.x);
}

// =====================================================================
// fp16x2-split (3-product) tensor-core GEMM: C = (A[M,K]*B[N,K]^T)/BSCALE
// CTA tile 64x128, 128 threads, 4 warps (2x2), warp tile 32x64
// -> per kstep: 48 MMA vs 12 ldsm (4:1). K staged in tiles of 32 via
// cp.async (double-buffered 48KB), 3 CTAs/SM (144KB smem, 12 warps/SM).
// EPI=0: store fp32 C. EPI=1: +bias+gumbel+argmax. EPI=2: fp32 C + h planes.
// =====================================================================
template<int EPI, bool NG>
__global__ __launch_bounds__(128, 3)
void bgemm(const uint16_t* __restrict__ A0, size_t sA0, const uint16_t* __restrict__ B0, size_t sB0,
           float* C0, int K0,
           const uint16_t* __restrict__ A1, size_t sA1, const uint16_t* __restrict__ B1, size_t sB1,
           float* C1, int K1,
           int Nn, const float* __restrict__ bout, const float* __restrict__ gumbel, int step,
           uint16_t* hpl)
{
    const uint16_t* A; const uint16_t* B; float* C; int K; size_t sA, sB;
    if (blockIdx.z == 0) { A = A0; sA = sA0; B = B0; sB = sB0; C = C0; K = K0; }
    else                 { A = A1; sA = sA1; B = B1; sB = sB1; C = C1; K = K1; }

    extern __shared__ uint8_t dynraw[];
    unsigned dynb = (unsigned)__cvta_generic_to_shared(dynraw);
    dynb = (dynb + 1023u) & ~1023u;
    __shared__ unsigned long long rowmax[64];

    const int tid  = threadIdx.x;
    const int lane = tid & 31;
    const int wid  = tid >> 5;
    const int wm = wid >> 1;          // 0..1 (rows wm*32)
    const int wn = wid & 1;           // 0..1 (cols wn*64)
    const int gid = lane >> 2;        // 0..7
    const int tig = lane & 3;         // 0..3
    const int bm = blockIdx.y * 64;
    const int bn = blockIdx.x * 128;

    // ---- staging ids (128 threads) ----
    // A: 64 rows x 4 chunks x 2 planes; thread: row=tid>>1, chunks cA, cA+1
    const int rowA = tid >> 1, cA = (tid & 1) * 2;
    const unsigned soffA0 = (unsigned)(rowA * 64 + (((cA)     ^ ((rowA >> 1) & 3)) << 4));
    const unsigned soffA1 = (unsigned)(rowA * 64 + (((cA + 1) ^ ((rowA >> 1) & 3)) << 4));
    const uint16_t* Agp = A + (size_t)(bm + rowA) * K + cA * 8;
    // B: 128 rows x 4 chunks x 2 planes; thread: row=tid, all 4 chunks
    const int rowB = tid;
    unsigned soffB[4];
#pragma unroll
    for (int c = 0; c < 4; ++c)
        soffB[c] = (unsigned)(rowB * 64 + ((c ^ ((rowB >> 1) & 3)) << 4));
    const uint16_t* Bgp = B + (size_t)(bn + rowB) * K;
    const unsigned nsz = (!NG || (bn + rowB) < Nn) ? 16u : 0u;

    // ---- ldmatrix per-lane offsets (kstep 0); XOR 32 selects kstep 1 ----
    unsigned aOff[2], bOff[4];
    {
        const int ra = wm * 32 + (lane & 7) + ((lane >> 3) & 1) * 8;
        const int ca = (lane >> 4) & 1;
#pragma unroll
        for (int mf = 0; mf < 2; ++mf) {
            int r = ra + mf * 16;
            aOff[mf] = (unsigned)(r * 64 + ((ca ^ ((r >> 1) & 3)) << 4));
        }
        const int rb = wn * 64 + ((lane >> 4) & 1) * 8 + (lane & 7);
        const int cb = (lane >> 3) & 1;
#pragma unroll
        for (int nfp = 0; nfp < 4; ++nfp) {
            int r = rb + nfp * 16;
            bOff[nfp] = (unsigned)(r * 64 + ((cb ^ ((r >> 1) & 3)) << 4));
        }
    }

    float4 acc[2][8];
#pragma unroll
    for (int i = 0; i < 2; i++)
#pragma unroll
        for (int j = 0; j < 8; j++) acc[i][j] = make_float4(0.f, 0.f, 0.f, 0.f);

    // smem per stage: A planes @ +0,+4096; B planes @ +8192,+16384; stage stride 24576
    auto STAGE = [&](int kt, int buf) {
        const unsigned base = dynb + (unsigned)buf * 24576u;
        const uint16_t* ap = Agp + kt * 32;
#pragma unroll
        for (int p = 0; p < 2; ++p) {
            cpa16(base + (unsigned)p * 4096u + soffA0, ap + (size_t)p * sA,     16u);
            cpa16(base + (unsigned)p * 4096u + soffA1, ap + (size_t)p * sA + 8, 16u);
        }
        const unsigned bb = base + 8192u;
        const uint16_t* bp = Bgp + kt * 32;
#pragma unroll
        for (int p = 0; p < 2; ++p)
#pragma unroll
            for (int c = 0; c < 4; ++c)
                cpa16(bb + (unsigned)p * 8192u + soffB[c], bp + (size_t)p * sB + c * 8, nsz);
        cpa_commit();
    };

    if (EPI == 1 && tid < 64) rowmax[tid] = 0ull;
    STAGE(0, 0);
    cpa_wait0();
    __syncthreads();

    const int KT = K >> 5;
    for (int kt = 0; kt < KT; ++kt) {
        if (kt + 1 < KT) STAGE(kt + 1, (kt + 1) & 1);

        const unsigned ab = dynb + (unsigned)(kt & 1) * 24576u;
        const unsigned bb = ab + 8192u;
#pragma unroll
        for (int kstep = 0; kstep < 2; ++kstep) {
            const unsigned kx = (unsigned)kstep << 5;
            uint32_t aF[2][2][4];
#pragma unroll
            for (int p = 0; p < 2; ++p)
#pragma unroll
                for (int mf = 0; mf < 2; ++mf)
                    ldsm4(aF[p][mf][0], aF[p][mf][1], aF[p][mf][2], aF[p][mf][3],
                          ab + (unsigned)p * 4096u + (aOff[mf] ^ kx));

            uint32_t bF[8][2];
            auto LDB = [&](int p) {
#pragma unroll
                for (int nfp = 0; nfp < 4; ++nfp) {
                    uint32_t r0, r1, r2, r3;
                    ldsm4(r0, r1, r2, r3, bb + (unsigned)p * 8192u + (bOff[nfp] ^ kx));
                    bF[2 * nfp][0] = r0;     bF[2 * nfp][1] = r1;
                    bF[2 * nfp + 1][0] = r2; bF[2 * nfp + 1][1] = r3;
                }
            };
            auto PROD = [&](int ap) {
#pragma unroll
                for (int mf = 0; mf < 2; ++mf)
#pragma unroll
                    for (int nf = 0; nf < 8; ++nf)
                        mma_f16(acc[mf][nf], aF[ap][mf], bF[nf]);
            };
            // smallest terms first, a0*b0 last
            LDB(1); PROD(0);            // a0*b1
            LDB(0); PROD(1); PROD(0);   // a1*b0, a0*b0
        }
        cpa_wait0();
        __syncthreads();
    }

    // undo B pre-scale
#pragma unroll
    for (int i = 0; i < 2; i++)
#pragma unroll
        for (int j = 0; j < 8; j++) {
            acc[i][j].x *= INVBSC; acc[i][j].y *= INVBSC;
            acc[i][j].z *= INVBSC; acc[i][j].w *= INVBSC;
        }

    if (EPI == 0 || EPI == 2) {
#pragma unroll
        for (int mf = 0; mf < 2; ++mf) {
            const int row = bm + wm * 32 + mf * 16 + gid;
#pragma unroll
            for (int nf = 0; nf < 8; ++nf) {
                const int col = bn + wn * 64 + nf * 8 + 2 * tig;
                float4 v = acc[mf][nf];
                *(float2*)(C + (size_t)row * Nn + col)       = make_float2(v.x, v.y);
                *(float2*)(C + (size_t)(row + 8) * Nn + col) = make_float2(v.z, v.w);
                if (EPI == 2) {
                    const long PSH = (long)NB * DHID / 2;
                    uint32_t* d = (uint32_t*)hpl;
                    uint32_t w0, w1;
                    split2(v.x, v.y, w0, w1);
                    long o = ((long)row * Nn + col) >> 1;
                    d[o] = w0; d[o + PSH] = w1;
                    split2(v.z, v.w, w0, w1);
                    o = ((long)(row + 8) * Nn + col) >> 1;
                    d[o] = w0; d[o + PSH] = w1;
                }
            }
        }
    } else {
        // fused +bias +gumbel + packed argmax
#pragma unroll
        for (int mf = 0; mf < 2; ++mf) {
            const int lm0 = wm * 32 + mf * 16 + gid;
            const int m0 = bm + lm0;
            unsigned long long best0 = 0ull, best1 = 0ull;
#pragma unroll
            for (int nf = 0; nf < 8; ++nf) {
                const int col = bn + wn * 64 + nf * 8 + 2 * tig;
                if (!NG || col < Nn) {      // Nn even, col even => pair fully valid
                    float2 bo = *(const float2*)(bout + col);
                    const float* g0 = gumbel + ((size_t)step * NB + m0) * (size_t)NV + col;
                    float2 ga = *(const float2*)g0;
                    float2 gb = *(const float2*)(g0 + (size_t)8 * NV);
                    float4 v = acc[mf][nf];
                    unsigned long long p;
                    p = packmax(v.x + bo.x + ga.x, col);     if (p > best0) best0 = p;
                    p = packmax(v.y + bo.y + ga.y, col + 1); if (p > best0) best0 = p;
                    p = packmax(v.z + bo.x + gb.x, col);     if (p > best1) best1 = p;
                    p = packmax(v.w + bo.y + gb.y, col + 1); if (p > best1) best1 = p;
                }
            }
            if (best0) atomicMax(&rowmax[lm0], best0);
            if (best1) atomicMax(&rowmax[lm0 + 8], best1);
        }
        __syncthreads();
        if (tid < 64 && rowmax[tid])
            atomicMax(&g_amax[bm + tid], rowmax[tid]);
    }
}

// ---------------- GRU elementwise: h_new (fp32 + fp16 planes) ----------------
__global__ void gru_elem(const float* __restrict__ b_ih, const float* __restrict__ b_hh,
                         const float* __restrict__ hOld, float* __restrict__ hNew,
                         uint16_t* __restrict__ hpl)
{
    int idx = blockIdx.x * blockDim.x + threadIdx.x;
    int m = idx >> 8;
    int j = (idx & 255) * 4;
    const float* G1 = g_G1 + (size_t)m * (3 * DHID);
    const float* G2 = g_G2 + (size_t)m * (3 * DHID);

    float4 ir = *(const float4*)(G1 + j);
    float4 iz = *(const float4*)(G1 + DHID + j);
    float4 in_ = *(const float4*)(G1 + 2 * DHID + j);
    float4 hr = *(const float4*)(G2 + j);
    float4 hz = *(const float4*)(G2 + DHID + j);
    float4 hn = *(const float4*)(G2 + 2 * DHID + j);
    float4 bir = *(const float4*)(b_ih + j);
    float4 biz = *(const float4*)(b_ih + DHID + j);
    float4 bin = *(const float4*)(b_ih + 2 * DHID + j);
    float4 bhr = *(const float4*)(b_hh + j);
    float4 bhz = *(const float4*)(b_hh + DHID + j);
    float4 bhn = *(const float4*)(b_hh + 2 * DHID + j);
    float4 ho = *(const float4*)(hOld + (size_t)m * DHID + j);

    float4 res;
#define GRU1(c) { \
        float r = 1.f / (1.f + expf(-((ir.c + bir.c) + (hr.c + bhr.c)))); \
        float z = 1.f / (1.f + expf(-((iz.c + biz.c) + (hz.c + bhz.c)))); \
        float n = tanhf((in_.c + bin.c) + r * (hn.c + bhn.c)); \
        res.c = (1.f - z) * n + z * ho.c; }
    GRU1(x) GRU1(y) GRU1(z) GRU1(w)
#undef GRU1
    *(float4*)(hNew + (size_t)m * DHID + j) = res;

    const long PSH = (long)NB * DHID / 2;
    uint32_t a0, a1, b0, b1;
    split2(res.x, res.y, a0, a1);
    split2(res.z, res.w, b0, b1);
    uint32_t* d = (uint32_t*)hpl;
    long o = ((long)m * DHID + j) >> 1;
    d[o] = a0;       d[o + 1] = b0;
    d[o + PSH] = a1; d[o + 1 + PSH] = b1;
}

// ---------------- finalize step: decode argmax, one-hot, next-x planes ----------------
__global__ void finalize_kernel(const float* __restrict__ emb, float* __restrict__ out, int s) {
    int b = blockIdx.x;
    __shared__ int stok;
    if (threadIdx.x == 0) {
        unsigned long long p = g_amax[b];
        int t = (int)(0xFFFFFFFFu - (unsigned)(p & 0xFFFFFFFFull));
        stok = t;
        g_tok[s * NB + b] = t;
        g_amax[b] = 0ull;
        out[((size_t)b * NS + s) * NV + t] = 1.0f;
    }
    __syncthreads();
    write_x_planes(emb, stok, b, threadIdx.x);
}

// ---------------- msg_lens: last EOS index + 1, else S ----------------
__global__ void lens_kernel(float* __restrict__ out, int out_size) {
    int b = threadIdx.x;
    int len = NS;
    for (int s = NS - 1; s >= 0; --s) {
        if (g_tok[s * NB + b] == EOS_TOK) { len = s + 1; break; }
    }
    if (out_size >= NB * NS * NV + NB)
        out[(size_t)NB * NS * NV + b] = (float)len;
}

// ---------------- launch ----------------
extern "C" void kernel_launch(void* const* d_in, const int* in_sizes, int n_in,
                              void* d_out, int out_size)
{
    const float* image = (const float*)d_in[0];
    const float* W_b   = (const float*)d_in[1];
    const float* emb   = (const float*)d_in[2];
    const float* w_ih  = (const float*)d_in[3];
    const float* w_hh  = (const float*)d_in[4];
    const float* b_ih  = (const float*)d_in[5];
    const float* b_hh  = (const float*)d_in[6];
    const float* W_out = (const float*)d_in[7];
    const float* b_out = (const float*)d_in[8];
    const float* gum   = (const float*)d_in[9];
    float* out = (float*)d_out;

    float *p_h0, *p_h1, *p_G1, *p_G2;
    uint16_t *pImg, *pWbT, *pWih, *pWhh, *pWout, *pX, *pHA, *pHB;
    cudaGetSymbolAddress((void**)&p_h0,  g_h0);
    cudaGetSymbolAddress((void**)&p_h1,  g_h1);
    cudaGetSymbolAddress((void**)&p_G1,  g_G1);
    cudaGetSymbolAddress((void**)&p_G2,  g_G2);
    cudaGetSymbolAddress((void**)&pImg,  g_pImg);
    cudaGetSymbolAddress((void**)&pWbT,  g_pWbT);
    cudaGetSymbolAddress((void**)&pWih,  g_pWih);
    cudaGetSymbolAddress((void**)&pWhh,  g_pWhh);
    cudaGetSymbolAddress((void**)&pWout, g_pWout);
    cudaGetSymbolAddress((void**)&pX,    g_pX);
    cudaGetSymbolAddress((void**)&pHA,   g_pHA);
    cudaGetSymbolAddress((void**)&pHB,   g_pHB);

    const int SHB = 2 * 24576 + 1024;   // double-buffered stages + alignment pad
    cudaFuncSetAttribute(bgemm<0, false>, cudaFuncAttributeMaxDynamicSharedMemorySize, SHB);
    cudaFuncSetAttribute(bgemm<1, true>,  cudaFuncAttributeMaxDynamicSharedMemorySize, SHB);
    cudaFuncSetAttribute(bgemm<2, false>, cudaFuncAttributeMaxDynamicSharedMemorySize, SHB);

    // zero the one-hot region
    long long n4 = (long long)NB * NS * NV / 4;
    zero_out<<<(unsigned)((n4 + 255) / 256), 256>>>((float4*)out, n4);

    // one-time: weight/activation pre-splits (weights scaled by BSCALE)
    transpose_split_wb<<<dim3(DIMG / 32, DHID / 32), dim3(32, 8)>>>(W_b);
    {
        long n2;
        n2 = (long)3 * DHID * DEMB / 2;
        split_mat<<<(unsigned)((n2 + 255) / 256), 256>>>(w_ih, pWih, n2, BSCALE);
        n2 = (long)3 * DHID * DHID / 2;
        split_mat<<<(unsigned)((n2 + 255) / 256), 256>>>(w_hh, pWhh, n2, BSCALE);
        n2 = (long)NV * DHID / 2;
        split_mat<<<(unsigned)((n2 + 255) / 256), 256>>>(W_out, pWout, n2, BSCALE);
        n2 = (long)NB * DIMG / 2;
        split_mat<<<(unsigned)((n2 + 255) / 256), 256>>>(image, pImg, n2, 1.0f);
    }
    init_kernel<<<NB, 128>>>(emb);

    const size_t sImg  = (size_t)NB * DIMG;
    const size_t sWbT  = (size_t)DHID * DIMG;
    const size_t sWih  = (size_t)3 * DHID * DEMB;
    const size_t sWhh  = (size_t)3 * DHID * DHID;
    const size_t sWout = (size_t)NV * DHID;
    const size_t sX    = (size_t)NB * DEMB;
    const size_t sH    = (size_t)NB * DHID;

    // h0 = image @ W_b -> g_h0 fp32 + pHA planes
    bgemm<2, false><<<dim3(DHID / 128, NB / 64, 1), 128, SHB>>>(
        pImg, sImg, pWbT, sWbT, p_h0, DIMG,
        pImg, sImg, pWbT, sWbT, p_h0, DIMG,
        DHID, nullptr, nullptr, 0, pHA);

    for (int s = 0; s < NS; ++s) {
        const float* hc = (s & 1) ? p_h1 : p_h0;
        float*       hn = (s & 1) ? p_h0 : p_h1;
        uint16_t* pHc = (s & 1) ? pHB : pHA;
        uint16_t* pHn = (s & 1) ? pHA : pHB;

        // gates: z=0 -> G1 = x @ w_ih^T (K=512); z=1 -> G2 = h @ w_hh^T (K=1024)
        bgemm<0, false><<<dim3(3 * DHID / 128, NB / 64, 2), 128, SHB>>>(
            pX,  sX, pWih, sWih, p_G1, DEMB,
            pHc, sH, pWhh, sWhh, p_G2, DHID,
            3 * DHID, nullptr, nullptr, 0, nullptr);
        gru_elem<<<(NB * DHID / 4) / 256, 256>>>(b_ih, b_hh, hc, hn, pHn);
        // logits + bias + gumbel + argmax
        bgemm<1, true><<<dim3((NV + 127) / 128, NB / 64, 1), 128, SHB>>>(
            pHn, sH, pWout, sWout, nullptr, DHID,
            pHn, sH, pWout, sWout, nullptr, DHID,
            NV, b_out, gum, s, nullptr);
        finalize_kernel<<<NB, 128>>>(emb, out, s);
    }

    lens_kernel<<<1, 256>>>(out, out_size);
}

// round 15
// speedup vs baseline: 1.3704x; 1.3704x over previous
#include <cuda_runtime.h>
#include <cuda_fp16.h>
#include <cstdint>

#define NB 256
#define NS 32
#define NV 10000
#define DEMB 512
#define DHID 1024
#define DIMG 2048
#define BOS_TOK 1
#define EOS_TOK 2

// B-plane pre-scale (exact power of two) to keep fp16 low-split out of subnormals
#define BSCALE 256.0f
#define INVBSC 0.00390625f

// ---------------- device scratch (static, no allocations) ----------------
__device__ float g_h0[NB * DHID];
__device__ float g_h1[NB * DHID];
__device__ float g_G1[NB * 3 * DHID];
__device__ float g_G2[NB * 3 * DHID];
__device__ unsigned long long g_amax[NB];
__device__ int g_tok[NS * NB];

// fp16 2-split planes (plane p at offset p*planeElems). Weights scaled by BSCALE.
__device__ uint16_t g_pImg [2u * NB * DIMG];
__device__ uint16_t g_pWbT [2u * DHID * DIMG];
__device__ uint16_t g_pWih [2u * 3 * DHID * DEMB];
__device__ uint16_t g_pWhh [2u * 3 * DHID * DHID];
__device__ uint16_t g_pWout[2u * NV * DHID];
__device__ uint16_t g_pX   [2u * NB * DEMB];
__device__ uint16_t g_pHA  [2u * NB * DHID];
__device__ uint16_t g_pHB  [2u * NB * DHID];

// order-preserving (float,index) pack; max => max value, ties => smallest index
__device__ __forceinline__ unsigned long long packmax(float v, int idx) {
    unsigned int b = __float_as_uint(v);
    b = (b & 0x80000000u) ? ~b : (b | 0x80000000u);
    return ((unsigned long long)b << 32) | (unsigned long long)(0xFFFFFFFFu - (unsigned)idx);
}

// ---------------- fp16 2-way split helpers ----------------
__device__ __forceinline__ uint32_t packh2(float hi, float lo) {
    uint32_t r;
    asm("cvt.rn.f16x2.f32 %0, %1, %2;" : "=r"(r) : "f"(hi), "f"(lo));
    return r;
}
__device__ __forceinline__ void split2(float x0, float x1, uint32_t& w0, uint32_t& w1) {
    w0 = packh2(x1, x0);
    __half2 h2 = *reinterpret_cast<const __half2*>(&w0);
    float r0 = x0 - __low2float(h2);
    float r1 = x1 - __high2float(h2);
    w1 = packh2(r1, r0);
}

// ---------------- mma / ldmatrix / cp.async ----------------
__device__ __forceinline__ void mma_f16(float4& d, const uint32_t* a, const uint32_t* b) {
    asm volatile(
        "mma.sync.aligned.m16n8k16.row.col.f32.f16.f16.f32 "
        "{%0,%1,%2,%3}, {%4,%5,%6,%7}, {%8,%9}, {%0,%1,%2,%3};"
        : "+f"(d.x), "+f"(d.y), "+f"(d.z), "+f"(d.w)
        : "r"(a[0]), "r"(a[1]), "r"(a[2]), "r"(a[3]), "r"(b[0]), "r"(b[1]));
}
__device__ __forceinline__ void ldsm4(uint32_t& r0, uint32_t& r1, uint32_t& r2, uint32_t& r3,
                                      unsigned addr) {
    asm volatile("ldmatrix.sync.aligned.m8n8.x4.shared.b16 {%0,%1,%2,%3}, [%4];"
                 : "=r"(r0), "=r"(r1), "=r"(r2), "=r"(r3) : "r"(addr));
}
__device__ __forceinline__ void cpa16(unsigned dst, const void* src, unsigned srcsz) {
    asm volatile("cp.async.cg.shared.global [%0], [%1], 16, %2;"
                 :: "r"(dst), "l"(src), "r"(srcsz));
}
__device__ __forceinline__ void cpa_commit() {
    asm volatile("cp.async.commit_group;" ::: "memory");
}
__device__ __forceinline__ void cpa_wait0() {
    asm volatile("cp.async.wait_group 0;" ::: "memory");
}

// ---------------- one-time: split a matrix into 2 fp16 planes (optional scale) ----------------
__global__ void split_mat(const float* __restrict__ src, uint16_t* __restrict__ dst, long n2, float sc) {
    long i = (long)blockIdx.x * blockDim.x + threadIdx.x;
    if (i >= n2) return;
    float2 v = ((const float2*)src)[i];
    uint32_t w0, w1;
    split2(v.x * sc, v.y * sc, w0, w1);
    uint32_t* d = (uint32_t*)dst;
    d[i] = w0; d[i + n2] = w1;
}

// ---------------- one-time: W_b transpose + split (scaled) ----------------
__global__ void transpose_split_wb(const float* __restrict__ Wb) {
    __shared__ float t[32][33];
    int k0 = blockIdx.x * 32;
    int n0 = blockIdx.y * 32;
    for (int i = threadIdx.y; i < 32; i += 8)
        t[i][threadIdx.x] = Wb[(size_t)(k0 + i) * DHID + n0 + threadIdx.x];
    __syncthreads();
    const size_t PS = (size_t)DHID * DIMG;
    for (int i = threadIdx.y; i < 32; i += 8) {
        float v = t[threadIdx.x][i] * BSCALE;
        uint32_t w0, w1;
        split2(v, 0.f, w0, w1);
        size_t o = (size_t)(n0 + i) * DIMG + k0 + threadIdx.x;
        g_pWbT[o]      = (uint16_t)(w0 & 0xFFFF);
        g_pWbT[o + PS] = (uint16_t)(w1 & 0xFFFF);
    }
}

// ---------------- zero the one-hot output ----------------
__global__ void zero_out(float4* o, long long n4) {
    long long i = (long long)blockIdx.x * blockDim.x + threadIdx.x;
    if (i < n4) o[i] = make_float4(0.f, 0.f, 0.f, 0.f);
}

// ---------------- write relu(emb[token]) into g_pX planes (one row, 128 threads) ----------------
__device__ __forceinline__ void write_x_planes(const float* __restrict__ emb, int tok, int b, int tid) {
    const int k = tid * 4;
    float4 e = *(const float4*)(emb + (size_t)tok * DEMB + k);
    e.x = fmaxf(e.x, 0.f); e.y = fmaxf(e.y, 0.f);
    e.z = fmaxf(e.z, 0.f); e.w = fmaxf(e.w, 0.f);
    uint32_t a0, a1, b0, b1;
    split2(e.x, e.y, a0, a1);
    split2(e.z, e.w, b0, b1);
    const long PS = (long)NB * DEMB / 2;
    uint32_t* d = (uint32_t*)g_pX;
    long o = ((long)b * DEMB + k) >> 1;
    d[o] = a0;      d[o + 1] = b0;
    d[o + PS] = a1; d[o + 1 + PS] = b1;
}

// ---------------- init: x0 planes = relu(emb[BOS]), amax reset ----------------
__global__ void init_kernel(const float* __restrict__ emb) {
    int b = blockIdx.x;
    if (threadIdx.x == 0) g_amax[b] = 0ull;
    write_x_planes(emb, BOS_TOK, b, threadIdx.x);
}

// =====================================================================
// fp16x2-split (3-product) tensor-core GEMM: C = (A[M,K]*B[N,K]^T)/BSCALE
// CTA tile 64x128, 256 threads, 8 warps (2x4), warp tile 32x32.
// K staged in tiles of 32 via cp.async (double-buffered 48KB), 3 CTAs/SM
// (single-wave schedule: logits 316 CTAs <= 444 slots, gates 384 <= 444).
// EPI=0: store fp32 C. EPI=1: +bias+gumbel+argmax. EPI=2: fp32 C + h planes.
// =====================================================================
template<int EPI, bool NG>
__global__ __launch_bounds__(256, 3)
void bgemm(const uint16_t* __restrict__ A0, size_t sA0, const uint16_t* __restrict__ B0, size_t sB0,
           float* C0, int K0,
           const uint16_t* __restrict__ A1, size_t sA1, const uint16_t* __restrict__ B1, size_t sB1,
           float* C1, int K1,
           int Nn, const float* __restrict__ bout, const float* __restrict__ gumbel, int step,
           uint16_t* hpl)
{
    const uint16_t* A; const uint16_t* B; float* C; int K; size_t sA, sB;
    if (blockIdx.z == 0) { A = A0; sA = sA0; B = B0; sB = sB0; C = C0; K = K0; }
    else                 { A = A1; sA = sA1; B = B1; sB = sB1; C = C1; K = K1; }

    extern __shared__ uint8_t dynraw[];
    unsigned dynb = (unsigned)__cvta_generic_to_shared(dynraw);
    dynb = (dynb + 1023u) & ~1023u;
    __shared__ unsigned long long rowmax[64];

    const int tid  = threadIdx.x;
    const int lane = tid & 31;
    const int wid  = tid >> 5;
    const int wm = wid >> 2;          // 0..1
    const int wn = wid & 3;           // 0..3
    const int gid = lane >> 2;        // 0..7
    const int tig = lane & 3;         // 0..3
    const int bm = blockIdx.y * 64;
    const int bn = blockIdx.x * 128;

    // ---- staging ids: A 64 rows x 4 chunks; B 128 rows x 4 chunks (2/thread) ----
    const int rowA = tid >> 2, chA = tid & 3;
    const int rowB = tid >> 1, chB2 = (tid & 1) * 2;
    const unsigned soffA = (unsigned)(rowA * 64 + ((chA ^ ((rowA >> 1) & 3)) << 4));
    const unsigned soffB0 = (unsigned)(rowB * 64 + (((chB2)     ^ ((rowB >> 1) & 3)) << 4));
    const unsigned soffB1 = (unsigned)(rowB * 64 + (((chB2 + 1) ^ ((rowB >> 1) & 3)) << 4));

    const uint16_t* Agp = A + (size_t)(bm + rowA) * K + chA * 8;
    const uint16_t* Bgp = B + (size_t)(bn + rowB) * K + chB2 * 8;
    const unsigned nsz = (!NG || (bn + rowB) < Nn) ? 16u : 0u;

    // ---- ldmatrix per-lane offsets (kstep 0); XOR 32 selects kstep 1 ----
    unsigned aOff[2], bOff[2];
    {
        const int ra = wm * 32 + (lane & 7) + ((lane >> 3) & 1) * 8;
        const int ca = (lane >> 4) & 1;
#pragma unroll
        for (int mf = 0; mf < 2; ++mf) {
            int r = ra + mf * 16;
            aOff[mf] = (unsigned)(r * 64 + ((ca ^ ((r >> 1) & 3)) << 4));
        }
        const int rb = wn * 32 + ((lane >> 4) & 1) * 8 + (lane & 7);
        const int cb = (lane >> 3) & 1;
#pragma unroll
        for (int nfp = 0; nfp < 2; ++nfp) {
            int r = rb + nfp * 16;
            bOff[nfp] = (unsigned)(r * 64 + ((cb ^ ((r >> 1) & 3)) << 4));
        }
    }

    float4 acc[2][4];
#pragma unroll
    for (int i = 0; i < 2; i++)
#pragma unroll
        for (int j = 0; j < 4; j++) acc[i][j] = make_float4(0.f, 0.f, 0.f, 0.f);

    // smem layout per stage: A planes @ +0,+4096; B planes @ +8192,+16384; stage stride 24576
    auto STAGE = [&](int kt, int buf) {
        const unsigned base = dynb + (unsigned)buf * 24576u;
        const uint16_t* ap = Agp + kt * 32;
#pragma unroll
        for (int p = 0; p < 2; ++p)
            cpa16(base + (unsigned)p * 4096u + soffA, ap + (size_t)p * sA, 16u);
        const unsigned bb = base + 8192u;
        const uint16_t* bp = Bgp + kt * 32;
#pragma unroll
        for (int p = 0; p < 2; ++p) {
            cpa16(bb + (unsigned)p * 8192u + soffB0, bp + (size_t)p * sB,     nsz);
            cpa16(bb + (unsigned)p * 8192u + soffB1, bp + (size_t)p * sB + 8, nsz);
        }
        cpa_commit();
    };

    if (EPI == 1 && tid < 64) rowmax[tid] = 0ull;
    STAGE(0, 0);
    cpa_wait0();
    __syncthreads();

    const int KT = K >> 5;
    for (int kt = 0; kt < KT; ++kt) {
        if (kt + 1 < KT) STAGE(kt + 1, (kt + 1) & 1);

        const unsigned ab = dynb + (unsigned)(kt & 1) * 24576u;
        const unsigned bb = ab + 8192u;
#pragma unroll
        for (int kstep = 0; kstep < 2; ++kstep) {
            const unsigned kx = (unsigned)kstep << 5;
            uint32_t aF[2][2][4];
#pragma unroll
            for (int p = 0; p < 2; ++p)
#pragma unroll
                for (int mf = 0; mf < 2; ++mf)
                    ldsm4(aF[p][mf][0], aF[p][mf][1], aF[p][mf][2], aF[p][mf][3],
                          ab + (unsigned)p * 4096u + (aOff[mf] ^ kx));

            uint32_t bF[4][2];
            auto LDB = [&](int p) {
#pragma unroll
                for (int nfp = 0; nfp < 2; ++nfp) {
                    uint32_t r0, r1, r2, r3;
                    ldsm4(r0, r1, r2, r3, bb + (unsigned)p * 8192u + (bOff[nfp] ^ kx));
                    bF[2 * nfp][0] = r0;     bF[2 * nfp][1] = r1;
                    bF[2 * nfp + 1][0] = r2; bF[2 * nfp + 1][1] = r3;
                }
            };
            auto PROD = [&](int ap) {
#pragma unroll
                for (int mf = 0; mf < 2; ++mf)
#pragma unroll
                    for (int nf = 0; nf < 4; ++nf)
                        mma_f16(acc[mf][nf], aF[ap][mf], bF[nf]);
            };
            // smallest terms first, a0*b0 last
            LDB(1); PROD(0);            // a0*b1
            LDB(0); PROD(1); PROD(0);   // a1*b0, a0*b0
        }
        cpa_wait0();
        __syncthreads();
    }

    // undo B pre-scale
#pragma unroll
    for (int i = 0; i < 2; i++)
#pragma unroll
        for (int j = 0; j < 4; j++) {
            acc[i][j].x *= INVBSC; acc[i][j].y *= INVBSC;
            acc[i][j].z *= INVBSC; acc[i][j].w *= INVBSC;
        }

    if (EPI == 0 || EPI == 2) {
#pragma unroll
        for (int mf = 0; mf < 2; ++mf) {
            const int row = bm + wm * 32 + mf * 16 + gid;
#pragma unroll
            for (int nf = 0; nf < 4; ++nf) {
                const int col = bn + wn * 32 + nf * 8 + 2 * tig;
                float4 v = acc[mf][nf];
                *(float2*)(C + (size_t)row * Nn + col)       = make_float2(v.x, v.y);
                *(float2*)(C + (size_t)(row + 8) * Nn + col) = make_float2(v.z, v.w);
                if (EPI == 2) {
                    const long PSH = (long)NB * DHID / 2;
                    uint32_t* d = (uint32_t*)hpl;
                    uint32_t w0, w1;
                    split2(v.x, v.y, w0, w1);
                    long o = ((long)row * Nn + col) >> 1;
                    d[o] = w0; d[o + PSH] = w1;
                    split2(v.z, v.w, w0, w1);
                    o = ((long)(row + 8) * Nn + col) >> 1;
                    d[o] = w0; d[o + PSH] = w1;
                }
            }
        }
    } else {
        // fused +bias +gumbel + packed argmax
#pragma unroll
        for (int mf = 0; mf < 2; ++mf) {
            const int lm0 = wm * 32 + mf * 16 + gid;
            const int m0 = bm + lm0;
            unsigned long long best0 = 0ull, best1 = 0ull;
#pragma unroll
            for (int nf = 0; nf < 4; ++nf) {
                const int col = bn + wn * 32 + nf * 8 + 2 * tig;
                if (!NG || col < Nn) {      // Nn even, col even => pair fully valid
                    float2 bo = *(const float2*)(bout + col);
                    const float* g0 = gumbel + ((size_t)step * NB + m0) * (size_t)NV + col;
                    float2 ga = *(const float2*)g0;
                    float2 gb = *(const float2*)(g0 + (size_t)8 * NV);
                    float4 v = acc[mf][nf];
                    unsigned long long p;
                    p = packmax(v.x + bo.x + ga.x, col);     if (p > best0) best0 = p;
                    p = packmax(v.y + bo.y + ga.y, col + 1); if (p > best0) best0 = p;
                    p = packmax(v.z + bo.x + gb.x, col);     if (p > best1) best1 = p;
                    p = packmax(v.w + bo.y + gb.y, col + 1); if (p > best1) best1 = p;
                }
            }
            if (best0) atomicMax(&rowmax[lm0], best0);
            if (best1) atomicMax(&rowmax[lm0 + 8], best1);
        }
        __syncthreads();
        if (tid < 64 && rowmax[tid])
            atomicMax(&g_amax[bm + tid], rowmax[tid]);
    }
}

// ---------------- GRU elementwise: h_new (fp32 + fp16 planes) ----------------
__global__ void gru_elem(const float* __restrict__ b_ih, const float* __restrict__ b_hh,
                         const float* __restrict__ hOld, float* __restrict__ hNew,
                         uint16_t* __restrict__ hpl)
{
    int idx = blockIdx.x * blockDim.x + threadIdx.x;
    int m = idx >> 8;
    int j = (idx & 255) * 4;
    const float* G1 = g_G1 + (size_t)m * (3 * DHID);
    const float* G2 = g_G2 + (size_t)m * (3 * DHID);

    float4 ir = *(const float4*)(G1 + j);
    float4 iz = *(const float4*)(G1 + DHID + j);
    float4 in_ = *(const float4*)(G1 + 2 * DHID + j);
    float4 hr = *(const float4*)(G2 + j);
    float4 hz = *(const float4*)(G2 + DHID + j);
    float4 hn = *(const float4*)(G2 + 2 * DHID + j);
    float4 bir = *(const float4*)(b_ih + j);
    float4 biz = *(const float4*)(b_ih + DHID + j);
    float4 bin = *(const float4*)(b_ih + 2 * DHID + j);
    float4 bhr = *(const float4*)(b_hh + j);
    float4 bhz = *(const float4*)(b_hh + DHID + j);
    float4 bhn = *(const float4*)(b_hh + 2 * DHID + j);
    float4 ho = *(const float4*)(hOld + (size_t)m * DHID + j);

    float4 res;
#define GRU1(c) { \
        float r = 1.f / (1.f + expf(-((ir.c + bir.c) + (hr.c + bhr.c)))); \
        float z = 1.f / (1.f + expf(-((iz.c + biz.c) + (hz.c + bhz.c)))); \
        float n = tanhf((in_.c + bin.c) + r * (hn.c + bhn.c)); \
        res.c = (1.f - z) * n + z * ho.c; }
    GRU1(x) GRU1(y) GRU1(z) GRU1(w)
#undef GRU1
    *(float4*)(hNew + (size_t)m * DHID + j) = res;

    const long PSH = (long)NB * DHID / 2;
    uint32_t a0, a1, b0, b1;
    split2(res.x, res.y, a0, a1);
    split2(res.z, res.w, b0, b1);
    uint32_t* d = (uint32_t*)hpl;
    long o = ((long)m * DHID + j) >> 1;
    d[o] = a0;       d[o + 1] = b0;
    d[o + PSH] = a1; d[o + 1 + PSH] = b1;
}

// ---------------- finalize step: decode argmax, one-hot, next-x planes ----------------
__global__ void finalize_kernel(const float* __restrict__ emb, float* __restrict__ out, int s) {
    int b = blockIdx.x;
    __shared__ int stok;
    if (threadIdx.x == 0) {
        unsigned long long p = g_amax[b];
        int t = (int)(0xFFFFFFFFu - (unsigned)(p & 0xFFFFFFFFull));
        stok = t;
        g_tok[s * NB + b] = t;
        g_amax[b] = 0ull;
        out[((size_t)b * NS + s) * NV + t] = 1.0f;
    }
    __syncthreads();
    write_x_planes(emb, stok, b, threadIdx.x);
}

// ---------------- msg_lens: last EOS index + 1, else S ----------------
__global__ void lens_kernel(float* __restrict__ out, int out_size) {
    int b = threadIdx.x;
    int len = NS;
    for (int s = NS - 1; s >= 0; --s) {
        if (g_tok[s * NB + b] == EOS_TOK) { len = s + 1; break; }
    }
    if (out_size >= NB * NS * NV + NB)
        out[(size_t)NB * NS * NV + b] = (float)len;
}

// ---------------- launch ----------------
extern "C" void kernel_launch(void* const* d_in, const int* in_sizes, int n_in,
                              void* d_out, int out_size)
{
    const float* image = (const float*)d_in[0];
    const float* W_b   = (const float*)d_in[1];
    const float* emb   = (const float*)d_in[2];
    const float* w_ih  = (const float*)d_in[3];
    const float* w_hh  = (const float*)d_in[4];
    const float* b_ih  = (const float*)d_in[5];
    const float* b_hh  = (const float*)d_in[6];
    const float* W_out = (const float*)d_in[7];
    const float* b_out = (const float*)d_in[8];
    const float* gum   = (const float*)d_in[9];
    float* out = (float*)d_out;

    float *p_h0, *p_h1, *p_G1, *p_G2;
    uint16_t *pImg, *pWbT, *pWih, *pWhh, *pWout, *pX, *pHA, *pHB;
    cudaGetSymbolAddress((void**)&p_h0,  g_h0);
    cudaGetSymbolAddress((void**)&p_h1,  g_h1);
    cudaGetSymbolAddress((void**)&p_G1,  g_G1);
    cudaGetSymbolAddress((void**)&p_G2,  g_G2);
    cudaGetSymbolAddress((void**)&pImg,  g_pImg);
    cudaGetSymbolAddress((void**)&pWbT,  g_pWbT);
    cudaGetSymbolAddress((void**)&pWih,  g_pWih);
    cudaGetSymbolAddress((void**)&pWhh,  g_pWhh);
    cudaGetSymbolAddress((void**)&pWout, g_pWout);
    cudaGetSymbolAddress((void**)&pX,    g_pX);
    cudaGetSymbolAddress((void**)&pHA,   g_pHA);
    cudaGetSymbolAddress((void**)&pHB,   g_pHB);

    const int SHB = 2 * 24576 + 1024;   // double-buffered stages + alignment pad
    cudaFuncSetAttribute(bgemm<0, false>, cudaFuncAttributeMaxDynamicSharedMemorySize, SHB);
    cudaFuncSetAttribute(bgemm<1, true>,  cudaFuncAttributeMaxDynamicSharedMemorySize, SHB);
    cudaFuncSetAttribute(bgemm<2, false>, cudaFuncAttributeMaxDynamicSharedMemorySize, SHB);

    // zero the one-hot region
    long long n4 = (long long)NB * NS * NV / 4;
    zero_out<<<(unsigned)((n4 + 255) / 256), 256>>>((float4*)out, n4);

    // one-time: weight/activation pre-splits (weights scaled by BSCALE)
    transpose_split_wb<<<dim3(DIMG / 32, DHID / 32), dim3(32, 8)>>>(W_b);
    {
        long n2;
        n2 = (long)3 * DHID * DEMB / 2;
        split_mat<<<(unsigned)((n2 + 255) / 256), 256>>>(w_ih, pWih, n2, BSCALE);
        n2 = (long)3 * DHID * DHID / 2;
        split_mat<<<(unsigned)((n2 + 255) / 256), 256>>>(w_hh, pWhh, n2, BSCALE);
        n2 = (long)NV * DHID / 2;
        split_mat<<<(unsigned)((n2 + 255) / 256), 256>>>(W_out, pWout, n2, BSCALE);
        n2 = (long)NB * DIMG / 2;
        split_mat<<<(unsigned)((n2 + 255) / 256), 256>>>(image, pImg, n2, 1.0f);
    }
    init_kernel<<<NB, 128>>>(emb);

    const size_t sImg  = (size_t)NB * DIMG;
    const size_t sWbT  = (size_t)DHID * DIMG;
    const size_t sWih  = (size_t)3 * DHID * DEMB;
    const size_t sWhh  = (size_t)3 * DHID * DHID;
    const size_t sWout = (size_t)NV * DHID;
    const size_t sX    = (size_t)NB * DEMB;
    const size_t sH    = (size_t)NB * DHID;

    // h0 = image @ W_b -> g_h0 fp32 + pHA planes
    bgemm<2, false><<<dim3(DHID / 128, NB / 64, 1), 256, SHB>>>(
        pImg, sImg, pWbT, sWbT, p_h0, DIMG,
        pImg, sImg, pWbT, sWbT, p_h0, DIMG,
        DHID, nullptr, nullptr, 0, pHA);

    for (int s = 0; s < NS; ++s) {
        const float* hc = (s & 1) ? p_h1 : p_h0;
        float*       hn = (s & 1) ? p_h0 : p_h1;
        uint16_t* pHc = (s & 1) ? pHB : pHA;
        uint16_t* pHn = (s & 1) ? pHA : pHB;

        // gates: z=0 -> G1 = x @ w_ih^T (K=512); z=1 -> G2 = h @ w_hh^T (K=1024)
        bgemm<0, false><<<dim3(3 * DHID / 128, NB / 64, 2), 256, SHB>>>(
            pX,  sX, pWih, sWih, p_G1, DEMB,
            pHc, sH, pWhh, sWhh, p_G2, DHID,
            3 * DHID, nullptr, nullptr, 0, nullptr);
        gru_elem<<<(NB * DHID / 4) / 256, 256>>>(b_ih, b_hh, hc, hn, pHn);
        // logits + bias + gumbel + argmax
        bgemm<1, true><<<dim3((NV + 127) / 128, NB / 64, 1), 256, SHB>>>(
            pHn, sH, pWout, sWout, nullptr, DHID,
            pHn, sH, pWout, sWout, nullptr, DHID,
            NV, b_out, gum, s, nullptr);
        finalize_kernel<<<NB, 128>>>(emb, out, s);
    }

    lens_kernel<<<1, 256>>>(out, out_size);
}

// round 16
// speedup vs baseline: 1.5656x; 1.1424x over previous
#include <cuda_runtime.h>
#include <cuda_fp16.h>
#include <cstdint>

#define NB 256
#define NS 32
#define NV 10000
#define DEMB 512
#define DHID 1024
#define DIMG 2048
#define BOS_TOK 1
#define EOS_TOK 2

// B-plane pre-scale (exact power of two) to keep fp16 low-split out of subnormals
#define BSCALE 256.0f
#define INVBSC 0.00390625f

// ---------------- device scratch (static, no allocations) ----------------
__device__ float g_h0[NB * DHID];
__device__ float g_h1[NB * DHID];
__device__ float g_G1[NB * 3 * DHID];
__device__ float g_G2[NB * 3 * DHID];
__device__ unsigned long long g_amax[NB];
__device__ int g_tok[NS * NB];

// fp16 2-split planes (plane p at offset p*planeElems). Weights scaled by BSCALE.
__device__ uint16_t g_pImg [2u * NB * DIMG];
__device__ uint16_t g_pWbT [2u * DHID * DIMG];
__device__ uint16_t g_pWih [2u * 3 * DHID * DEMB];
__device__ uint16_t g_pWhh [2u * 3 * DHID * DHID];
__device__ uint16_t g_pWout[2u * NV * DHID];
__device__ uint16_t g_pX   [2u * NB * DEMB];
__device__ uint16_t g_pHA  [2u * NB * DHID];
__device__ uint16_t g_pHB  [2u * NB * DHID];

// order-preserving (float,index) pack; max => max value, ties => smallest index
__device__ __forceinline__ unsigned long long packmax(float v, int idx) {
    unsigned int b = __float_as_uint(v);
    b = (b & 0x80000000u) ? ~b : (b | 0x80000000u);
    return ((unsigned long long)b << 32) | (unsigned long long)(0xFFFFFFFFu - (unsigned)idx);
}

// ---------------- fp16 2-way split helpers ----------------
__device__ __forceinline__ uint32_t packh2(float hi, float lo) {
    uint32_t r;
    asm("cvt.rn.f16x2.f32 %0, %1, %2;" : "=r"(r) : "f"(hi), "f"(lo));
    return r;
}
__device__ __forceinline__ void split2(float x0, float x1, uint32_t& w0, uint32_t& w1) {
    w0 = packh2(x1, x0);
    __half2 h2 = *reinterpret_cast<const __half2*>(&w0);
    float r0 = x0 - __low2float(h2);
    float r1 = x1 - __high2float(h2);
    w1 = packh2(r1, r0);
}

// ---------------- mma / ldmatrix / cp.async ----------------
__device__ __forceinline__ void mma_f16(float4& d, const uint32_t* a, const uint32_t* b) {
    asm volatile(
        "mma.sync.aligned.m16n8k16.row.col.f32.f16.f16.f32 "
        "{%0,%1,%2,%3}, {%4,%5,%6,%7}, {%8,%9}, {%0,%1,%2,%3};"
        : "+f"(d.x), "+f"(d.y), "+f"(d.z), "+f"(d.w)
        : "r"(a[0]), "r"(a[1]), "r"(a[2]), "r"(a[3]), "r"(b[0]), "r"(b[1]));
}
__device__ __forceinline__ void ldsm4(uint32_t& r0, uint32_t& r1, uint32_t& r2, uint32_t& r3,
                                      unsigned addr) {
    asm volatile("ldmatrix.sync.aligned.m8n8.x4.shared.b16 {%0,%1,%2,%3}, [%4];"
                 : "=r"(r0), "=r"(r1), "=r"(r2), "=r"(r3) : "r"(addr));
}
__device__ __forceinline__ void cpa16(unsigned dst, const void* src, unsigned srcsz) {
    asm volatile("cp.async.cg.shared.global [%0], [%1], 16, %2;"
                 :: "r"(dst), "l"(src), "r"(srcsz));
}
__device__ __forceinline__ void cpa_commit() {
    asm volatile("cp.async.commit_group;" ::: "memory");
}
__device__ __forceinline__ void cpa_wait0() {
    asm volatile("cp.async.wait_group 0;" ::: "memory");
}
__device__ __forceinline__ void cpa_wait1() {
    asm volatile("cp.async.wait_group 1;" ::: "memory");
}

// ---------------- one-time: split a matrix into 2 fp16 planes (optional scale) ----------------
__global__ void split_mat(const float* __restrict__ src, uint16_t* __restrict__ dst, long n2, float sc) {
    long i = (long)blockIdx.x * blockDim.x + threadIdx.x;
    if (i >= n2) return;
    float2 v = ((const float2*)src)[i];
    uint32_t w0, w1;
    split2(v.x * sc, v.y * sc, w0, w1);
    uint32_t* d = (uint32_t*)dst;
    d[i] = w0; d[i + n2] = w1;
}

// ---------------- one-time: W_b transpose + split (scaled) ----------------
__global__ void transpose_split_wb(const float* __restrict__ Wb) {
    __shared__ float t[32][33];
    int k0 = blockIdx.x * 32;
    int n0 = blockIdx.y * 32;
    for (int i = threadIdx.y; i < 32; i += 8)
        t[i][threadIdx.x] = Wb[(size_t)(k0 + i) * DHID + n0 + threadIdx.x];
    __syncthreads();
    const size_t PS = (size_t)DHID * DIMG;
    for (int i = threadIdx.y; i < 32; i += 8) {
        float v = t[threadIdx.x][i] * BSCALE;
        uint32_t w0, w1;
        split2(v, 0.f, w0, w1);
        size_t o = (size_t)(n0 + i) * DIMG + k0 + threadIdx.x;
        g_pWbT[o]      = (uint16_t)(w0 & 0xFFFF);
        g_pWbT[o + PS] = (uint16_t)(w1 & 0xFFFF);
    }
}

// ---------------- zero the one-hot output ----------------
__global__ void zero_out(float4* o, long long n4) {
    long long i = (long long)blockIdx.x * blockDim.x + threadIdx.x;
    if (i < n4) o[i] = make_float4(0.f, 0.f, 0.f, 0.f);
}

// ---------------- write relu(emb[token]) into g_pX planes (one row, 128 threads) ----------------
__device__ __forceinline__ void write_x_planes(const float* __restrict__ emb, int tok, int b, int tid) {
    const int k = tid * 4;
    float4 e = *(const float4*)(emb + (size_t)tok * DEMB + k);
    e.x = fmaxf(e.x, 0.f); e.y = fmaxf(e.y, 0.f);
    e.z = fmaxf(e.z, 0.f); e.w = fmaxf(e.w, 0.f);
    uint32_t a0, a1, b0, b1;
    split2(e.x, e.y, a0, a1);
    split2(e.z, e.w, b0, b1);
    const long PS = (long)NB * DEMB / 2;
    uint32_t* d = (uint32_t*)g_pX;
    long o = ((long)b * DEMB + k) >> 1;
    d[o] = a0;      d[o + 1] = b0;
    d[o + PS] = a1; d[o + 1 + PS] = b1;
}

// ---------------- init: x0 planes = relu(emb[BOS]), amax reset ----------------
__global__ void init_kernel(const float* __restrict__ emb) {
    int b = blockIdx.x;
    if (threadIdx.x == 0) g_amax[b] = 0ull;
    write_x_planes(emb, BOS_TOK, b, threadIdx.x);
}

// =====================================================================
// fp16x2-split (3-product) tensor-core GEMM: C = (A[M,K]*B[N,K]^T)/BSCALE
// CTA tile 64x128, 256 threads, 8 warps (2x4), warp tile 32x32.
// K staged in tiles of 32 via cp.async, TRIPLE-buffered (72KB) with
// wait_group 1 so each iteration's wait covers a stage issued a full
// iteration earlier (load latency fully hidden). 3 CTAs/SM.
// EPI=0: store fp32 C. EPI=1: +bias+gumbel+argmax. EPI=2: fp32 C + h planes.
// =====================================================================
template<int EPI, bool NG>
__global__ __launch_bounds__(256, 3)
void bgemm(const uint16_t* __restrict__ A0, size_t sA0, const uint16_t* __restrict__ B0, size_t sB0,
           float* C0, int K0,
           const uint16_t* __restrict__ A1, size_t sA1, const uint16_t* __restrict__ B1, size_t sB1,
           float* C1, int K1,
           int Nn, const float* __restrict__ bout, const float* __restrict__ gumbel, int step,
           uint16_t* hpl)
{
    const uint16_t* A; const uint16_t* B; float* C; int K; size_t sA, sB;
    if (blockIdx.z == 0) { A = A0; sA = sA0; B = B0; sB = sB0; C = C0; K = K0; }
    else                 { A = A1; sA = sA1; B = B1; sB = sB1; C = C1; K = K1; }

    extern __shared__ uint8_t dynraw[];
    unsigned dynb = (unsigned)__cvta_generic_to_shared(dynraw);
    dynb = (dynb + 127u) & ~127u;
    __shared__ unsigned long long rowmax[64];

    const int tid  = threadIdx.x;
    const int lane = tid & 31;
    const int wid  = tid >> 5;
    const int wm = wid >> 2;          // 0..1
    const int wn = wid & 3;           // 0..3
    const int gid = lane >> 2;        // 0..7
    const int tig = lane & 3;         // 0..3
    const int bm = blockIdx.y * 64;
    const int bn = blockIdx.x * 128;

    // ---- staging ids: A 64 rows x 4 chunks; B 128 rows x 4 chunks (2/thread) ----
    const int rowA = tid >> 2, chA = tid & 3;
    const int rowB = tid >> 1, chB2 = (tid & 1) * 2;
    const unsigned soffA = (unsigned)(rowA * 64 + ((chA ^ ((rowA >> 1) & 3)) << 4));
    const unsigned soffB0 = (unsigned)(rowB * 64 + (((chB2)     ^ ((rowB >> 1) & 3)) << 4));
    const unsigned soffB1 = (unsigned)(rowB * 64 + (((chB2 + 1) ^ ((rowB >> 1) & 3)) << 4));

    const uint16_t* Agp = A + (size_t)(bm + rowA) * K + chA * 8;
    const uint16_t* Bgp = B + (size_t)(bn + rowB) * K + chB2 * 8;
    const unsigned nsz = (!NG || (bn + rowB) < Nn) ? 16u : 0u;

    // ---- ldmatrix per-lane offsets (kstep 0); XOR 32 selects kstep 1 ----
    unsigned aOff[2], bOff[2];
    {
        const int ra = wm * 32 + (lane & 7) + ((lane >> 3) & 1) * 8;
        const int ca = (lane >> 4) & 1;
#pragma unroll
        for (int mf = 0; mf < 2; ++mf) {
            int r = ra + mf * 16;
            aOff[mf] = (unsigned)(r * 64 + ((ca ^ ((r >> 1) & 3)) << 4));
        }
        const int rb = wn * 32 + ((lane >> 4) & 1) * 8 + (lane & 7);
        const int cb = (lane >> 3) & 1;
#pragma unroll
        for (int nfp = 0; nfp < 2; ++nfp) {
            int r = rb + nfp * 16;
            bOff[nfp] = (unsigned)(r * 64 + ((cb ^ ((r >> 1) & 3)) << 4));
        }
    }

    float4 acc[2][4];
#pragma unroll
    for (int i = 0; i < 2; i++)
#pragma unroll
        for (int j = 0; j < 4; j++) acc[i][j] = make_float4(0.f, 0.f, 0.f, 0.f);

    // smem layout per stage (24576 B): A planes @ +0,+4096; B planes @ +8192,+16384
    auto STAGE = [&](int kt, int buf) {
        const unsigned base = dynb + (unsigned)buf * 24576u;
        const uint16_t* ap = Agp + kt * 32;
#pragma unroll
        for (int p = 0; p < 2; ++p)
            cpa16(base + (unsigned)p * 4096u + soffA, ap + (size_t)p * sA, 16u);
        const unsigned bb = base + 8192u;
        const uint16_t* bp = Bgp + kt * 32;
#pragma unroll
        for (int p = 0; p < 2; ++p) {
            cpa16(bb + (unsigned)p * 8192u + soffB0, bp + (size_t)p * sB,     nsz);
            cpa16(bb + (unsigned)p * 8192u + soffB1, bp + (size_t)p * sB + 8, nsz);
        }
        cpa_commit();
    };

    if (EPI == 1 && tid < 64) rowmax[tid] = 0ull;

    const int KT = K >> 5;
    // prologue: stages 0 and 1 in flight; guarantee stage 0 resident
    STAGE(0, 0);
    if (KT > 1) { STAGE(1, 1); cpa_wait1(); }
    else        { cpa_wait0(); }
    __syncthreads();

    int buf = 0;
    for (int kt = 0; kt < KT; ++kt) {
        const unsigned ab = dynb + (unsigned)buf * 24576u;
        const unsigned bb = ab + 8192u;
#pragma unroll
        for (int kstep = 0; kstep < 2; ++kstep) {
            const unsigned kx = (unsigned)kstep << 5;
            uint32_t aF[2][2][4];
#pragma unroll
            for (int p = 0; p < 2; ++p)
#pragma unroll
                for (int mf = 0; mf < 2; ++mf)
                    ldsm4(aF[p][mf][0], aF[p][mf][1], aF[p][mf][2], aF[p][mf][3],
                          ab + (unsigned)p * 4096u + (aOff[mf] ^ kx));

            uint32_t bF[4][2];
            auto LDB = [&](int p) {
#pragma unroll
                for (int nfp = 0; nfp < 2; ++nfp) {
                    uint32_t r0, r1, r2, r3;
                    ldsm4(r0, r1, r2, r3, bb + (unsigned)p * 8192u + (bOff[nfp] ^ kx));
                    bF[2 * nfp][0] = r0;     bF[2 * nfp][1] = r1;
                    bF[2 * nfp + 1][0] = r2; bF[2 * nfp + 1][1] = r3;
                }
            };
            auto PROD = [&](int ap) {
#pragma unroll
                for (int mf = 0; mf < 2; ++mf)
#pragma unroll
                    for (int nf = 0; nf < 4; ++nf)
                        mma_f16(acc[mf][nf], aF[ap][mf], bF[nf]);
            };
            // smallest terms first, a0*b0 last
            LDB(1); PROD(0);            // a0*b1
            LDB(0); PROD(1); PROD(0);   // a1*b0, a0*b0
        }

        // prefetch kt+2 into the third buffer
        if (kt + 2 < KT) {
            int buf2 = buf + 2; if (buf2 >= 3) buf2 -= 3;
            STAGE(kt + 2, buf2);
            cpa_wait1();                // stage kt+1 resident; kt+2 may be in flight
        } else {
            cpa_wait0();                // drain tail
        }
        __syncthreads();
        if (++buf == 3) buf = 0;
    }

    // undo B pre-scale
#pragma unroll
    for (int i = 0; i < 2; i++)
#pragma unroll
        for (int j = 0; j < 4; j++) {
            acc[i][j].x *= INVBSC; acc[i][j].y *= INVBSC;
            acc[i][j].z *= INVBSC; acc[i][j].w *= INVBSC;
        }

    if (EPI == 0 || EPI == 2) {
#pragma unroll
        for (int mf = 0; mf < 2; ++mf) {
            const int row = bm + wm * 32 + mf * 16 + gid;
#pragma unroll
            for (int nf = 0; nf < 4; ++nf) {
                const int col = bn + wn * 32 + nf * 8 + 2 * tig;
                float4 v = acc[mf][nf];
                *(float2*)(C + (size_t)row * Nn + col)       = make_float2(v.x, v.y);
                *(float2*)(C + (size_t)(row + 8) * Nn + col) = make_float2(v.z, v.w);
                if (EPI == 2) {
                    const long PSH = (long)NB * DHID / 2;
                    uint32_t* d = (uint32_t*)hpl;
                    uint32_t w0, w1;
                    split2(v.x, v.y, w0, w1);
                    long o = ((long)row * Nn + col) >> 1;
                    d[o] = w0; d[o + PSH] = w1;
                    split2(v.z, v.w, w0, w1);
                    o = ((long)(row + 8) * Nn + col) >> 1;
                    d[o] = w0; d[o + PSH] = w1;
                }
            }
        }
    } else {
        // fused +bias +gumbel + packed argmax
#pragma unroll
        for (int mf = 0; mf < 2; ++mf) {
            const int lm0 = wm * 32 + mf * 16 + gid;
            const int m0 = bm + lm0;
            unsigned long long best0 = 0ull, best1 = 0ull;
#pragma unroll
            for (int nf = 0; nf < 4; ++nf) {
                const int col = bn + wn * 32 + nf * 8 + 2 * tig;
                if (!NG || col < Nn) {      // Nn even, col even => pair fully valid
                    float2 bo = *(const float2*)(bout + col);
                    const float* g0 = gumbel + ((size_t)step * NB + m0) * (size_t)NV + col;
                    float2 ga = *(const float2*)g0;
                    float2 gb = *(const float2*)(g0 + (size_t)8 * NV);
                    float4 v = acc[mf][nf];
                    unsigned long long p;
                    p = packmax(v.x + bo.x + ga.x, col);     if (p > best0) best0 = p;
                    p = packmax(v.y + bo.y + ga.y, col + 1); if (p > best0) best0 = p;
                    p = packmax(v.z + bo.x + gb.x, col);     if (p > best1) best1 = p;
                    p = packmax(v.w + bo.y + gb.y, col + 1); if (p > best1) best1 = p;
                }
            }
            if (best0) atomicMax(&rowmax[lm0], best0);
            if (best1) atomicMax(&rowmax[lm0 + 8], best1);
        }
        __syncthreads();
        if (tid < 64 && rowmax[tid])
            atomicMax(&g_amax[bm + tid], rowmax[tid]);
    }
}

// ---------------- GRU elementwise: h_new (fp32 + fp16 planes) ----------------
__global__ void gru_elem(const float* __restrict__ b_ih, const float* __restrict__ b_hh,
                         const float* __restrict__ hOld, float* __restrict__ hNew,
                         uint16_t* __restrict__ hpl)
{
    int idx = blockIdx.x * blockDim.x + threadIdx.x;
    int m = idx >> 8;
    int j = (idx & 255) * 4;
    const float* G1 = g_G1 + (size_t)m * (3 * DHID);
    const float* G2 = g_G2 + (size_t)m * (3 * DHID);

    float4 ir = *(const float4*)(G1 + j);
    float4 iz = *(const float4*)(G1 + DHID + j);
    float4 in_ = *(const float4*)(G1 + 2 * DHID + j);
    float4 hr = *(const float4*)(G2 + j);
    float4 hz = *(const float4*)(G2 + DHID + j);
    float4 hn = *(const float4*)(G2 + 2 * DHID + j);
    float4 bir = *(const float4*)(b_ih + j);
    float4 biz = *(const float4*)(b_ih + DHID + j);
    float4 bin = *(const float4*)(b_ih + 2 * DHID + j);
    float4 bhr = *(const float4*)(b_hh + j);
    float4 bhz = *(const float4*)(b_hh + DHID + j);
    float4 bhn = *(const float4*)(b_hh + 2 * DHID + j);
    float4 ho = *(const float4*)(hOld + (size_t)m * DHID + j);

    float4 res;
#define GRU1(c) { \
        float r = 1.f / (1.f + expf(-((ir.c + bir.c) + (hr.c + bhr.c)))); \
        float z = 1.f / (1.f + expf(-((iz.c + biz.c) + (hz.c + bhz.c)))); \
        float n = tanhf((in_.c + bin.c) + r * (hn.c + bhn.c)); \
        res.c = (1.f - z) * n + z * ho.c; }
    GRU1(x) GRU1(y) GRU1(z) GRU1(w)
#undef GRU1
    *(float4*)(hNew + (size_t)m * DHID + j) = res;

    const long PSH = (long)NB * DHID / 2;
    uint32_t a0, a1, b0, b1;
    split2(res.x, res.y, a0, a1);
    split2(res.z, res.w, b0, b1);
    uint32_t* d = (uint32_t*)hpl;
    long o = ((long)m * DHID + j) >> 1;
    d[o] = a0;       d[o + 1] = b0;
    d[o + PSH] = a1; d[o + 1 + PSH] = b1;
}

// ---------------- finalize step: decode argmax, one-hot, next-x planes ----------------
__global__ void finalize_kernel(const float* __restrict__ emb, float* __restrict__ out, int s) {
    int b = blockIdx.x;
    __shared__ int stok;
    if (threadIdx.x == 0) {
        unsigned long long p = g_amax[b];
        int t = (int)(0xFFFFFFFFu - (unsigned)(p & 0xFFFFFFFFull));
        stok = t;
        g_tok[s * NB + b] = t;
        g_amax[b] = 0ull;
        out[((size_t)b * NS + s) * NV + t] = 1.0f;
    }
    __syncthreads();
    write_x_planes(emb, stok, b, threadIdx.x);
}

// ---------------- msg_lens: last EOS index + 1, else S ----------------
__global__ void lens_kernel(float* __restrict__ out, int out_size) {
    int b = threadIdx.x;
    int len = NS;
    for (int s = NS - 1; s >= 0; --s) {
        if (g_tok[s * NB + b] == EOS_TOK) { len = s + 1; break; }
    }
    if (out_size >= NB * NS * NV + NB)
        out[(size_t)NB * NS * NV + b] = (float)len;
}

// ---------------- launch ----------------
extern "C" void kernel_launch(void* const* d_in, const int* in_sizes, int n_in,
                              void* d_out, int out_size)
{
    const float* image = (const float*)d_in[0];
    const float* W_b   = (const float*)d_in[1];
    const float* emb   = (const float*)d_in[2];
    const float* w_ih  = (const float*)d_in[3];
    const float* w_hh  = (const float*)d_in[4];
    const float* b_ih  = (const float*)d_in[5];
    const float* b_hh  = (const float*)d_in[6];
    const float* W_out = (const float*)d_in[7];
    const float* b_out = (const float*)d_in[8];
    const float* gum   = (const float*)d_in[9];
    float* out = (float*)d_out;

    float *p_h0, *p_h1, *p_G1, *p_G2;
    uint16_t *pImg, *pWbT, *pWih, *pWhh, *pWout, *pX, *pHA, *pHB;
    cudaGetSymbolAddress((void**)&p_h0,  g_h0);
    cudaGetSymbolAddress((void**)&p_h1,  g_h1);
    cudaGetSymbolAddress((void**)&p_G1,  g_G1);
    cudaGetSymbolAddress((void**)&p_G2,  g_G2);
    cudaGetSymbolAddress((void**)&pImg,  g_pImg);
    cudaGetSymbolAddress((void**)&pWbT,  g_pWbT);
    cudaGetSymbolAddress((void**)&pWih,  g_pWih);
    cudaGetSymbolAddress((void**)&pWhh,  g_pWhh);
    cudaGetSymbolAddress((void**)&pWout, g_pWout);
    cudaGetSymbolAddress((void**)&pX,    g_pX);
    cudaGetSymbolAddress((void**)&pHA,   g_pHA);
    cudaGetSymbolAddress((void**)&pHB,   g_pHB);

    const int SHB = 3 * 24576 + 128;   // triple-buffered stages + alignment pad
    cudaFuncSetAttribute(bgemm<0, false>, cudaFuncAttributeMaxDynamicSharedMemorySize, SHB);
    cudaFuncSetAttribute(bgemm<1, true>,  cudaFuncAttributeMaxDynamicSharedMemorySize, SHB);
    cudaFuncSetAttribute(bgemm<2, false>, cudaFuncAttributeMaxDynamicSharedMemorySize, SHB);

    // zero the one-hot region
    long long n4 = (long long)NB * NS * NV / 4;
    zero_out<<<(unsigned)((n4 + 255) / 256), 256>>>((float4*)out, n4);

    // one-time: weight/activation pre-splits (weights scaled by BSCALE)
    transpose_split_wb<<<dim3(DIMG / 32, DHID / 32), dim3(32, 8)>>>(W_b);
    {
        long n2;
        n2 = (long)3 * DHID * DEMB / 2;
        split_mat<<<(unsigned)((n2 + 255) / 256), 256>>>(w_ih, pWih, n2, BSCALE);
        n2 = (long)3 * DHID * DHID / 2;
        split_mat<<<(unsigned)((n2 + 255) / 256), 256>>>(w_hh, pWhh, n2, BSCALE);
        n2 = (long)NV * DHID / 2;
        split_mat<<<(unsigned)((n2 + 255) / 256), 256>>>(W_out, pWout, n2, BSCALE);
        n2 = (long)NB * DIMG / 2;
        split_mat<<<(unsigned)((n2 + 255) / 256), 256>>>(image, pImg, n2, 1.0f);
    }
    init_kernel<<<NB, 128>>>(emb);

    const size_t sImg  = (size_t)NB * DIMG;
    const size_t sWbT  = (size_t)DHID * DIMG;
    const size_t sWih  = (size_t)3 * DHID * DEMB;
    const size_t sWhh  = (size_t)3 * DHID * DHID;
    const size_t sWout = (size_t)NV * DHID;
    const size_t sX    = (size_t)NB * DEMB;
    const size_t sH    = (size_t)NB * DHID;

    // h0 = image @ W_b -> g_h0 fp32 + pHA planes
    bgemm<2, false><<<dim3(DHID / 128, NB / 64, 1), 256, SHB>>>(
        pImg, sImg, pWbT, sWbT, p_h0, DIMG,
        pImg, sImg, pWbT, sWbT, p_h0, DIMG,
        DHID, nullptr, nullptr, 0, pHA);

    for (int s = 0; s < NS; ++s) {
        const float* hc = (s & 1) ? p_h1 : p_h0;
        float*       hn = (s & 1) ? p_h0 : p_h1;
        uint16_t* pHc = (s & 1) ? pHB : pHA;
        uint16_t* pHn = (s & 1) ? pHA : pHB;

        // gates: z=0 -> G1 = x @ w_ih^T (K=512); z=1 -> G2 = h @ w_hh^T (K=1024)
        bgemm<0, false><<<dim3(3 * DHID / 128, NB / 64, 2), 256, SHB>>>(
            pX,  sX, pWih, sWih, p_G1, DEMB,
            pHc, sH, pWhh, sWhh, p_G2, DHID,
            3 * DHID, nullptr, nullptr, 0, nullptr);
        gru_elem<<<(NB * DHID / 4) / 256, 256>>>(b_ih, b_hh, hc, hn, pHn);
        // logits + bias + gumbel + argmax
        bgemm<1, true><<<dim3((NV + 127) / 128, NB / 64, 1), 256, SHB>>>(
            pHn, sH, pWout, sWout, nullptr, DHID,
            pHn, sH, pWout, sWout, nullptr, DHID,
            NV, b_out, gum, s, nullptr);
        finalize_kernel<<<NB, 128>>>(emb, out, s);
    }

    lens_kernel<<<1, 256>>>(out, out_size);
}

// round 17
// speedup vs baseline: 1.6321x; 1.0425x over previous
#include <cuda_runtime.h>
#include <cuda_fp16.h>
#include <cstdint>

#define NB 256
#define NS 32
#define NV 10000
#define DEMB 512
#define DHID 1024
#define DIMG 2048
#define BOS_TOK 1
#define EOS_TOK 2

// B-plane pre-scale (exact power of two) to keep fp16 low-split out of subnormals
#define BSCALE 256.0f
#define INVBSC 0.00390625f

// ---------------- device scratch (static, no allocations) ----------------
__device__ float g_h0[NB * DHID];
__device__ float g_h1[NB * DHID];
__device__ float g_G1[NB * 3 * DHID];
__device__ float g_G2[NB * 3 * DHID];
__device__ unsigned long long g_amax[2 * NB];   // parity double-buffered
__device__ int g_tok[NS * NB];

// fp16 2-split planes (plane p at offset p*planeElems). Weights scaled by BSCALE.
__device__ uint16_t g_pImg [2u * NB * DIMG];
__device__ uint16_t g_pWbT [2u * DHID * DIMG];
__device__ uint16_t g_pWih [2u * 3 * DHID * DEMB];
__device__ uint16_t g_pWhh [2u * 3 * DHID * DHID];
__device__ uint16_t g_pWout[2u * NV * DHID];
__device__ uint16_t g_pHA  [2u * NB * DHID];
__device__ uint16_t g_pHB  [2u * NB * DHID];

// order-preserving (float,index) pack; max => max value, ties => smallest index
__device__ __forceinline__ unsigned long long packmax(float v, int idx) {
    unsigned int b = __float_as_uint(v);
    b = (b & 0x80000000u) ? ~b : (b | 0x80000000u);
    return ((unsigned long long)b << 32) | (unsigned long long)(0xFFFFFFFFu - (unsigned)idx);
}
__device__ __forceinline__ int unpack_tok(unsigned long long p) {
    return (int)(0xFFFFFFFFu - (unsigned)(p & 0xFFFFFFFFull));
}

// ---------------- fp16 2-way split helpers ----------------
__device__ __forceinline__ uint32_t packh2(float hi, float lo) {
    uint32_t r;
    asm("cvt.rn.f16x2.f32 %0, %1, %2;" : "=r"(r) : "f"(hi), "f"(lo));
    return r;
}
__device__ __forceinline__ void split2(float x0, float x1, uint32_t& w0, uint32_t& w1) {
    w0 = packh2(x1, x0);
    __half2 h2 = *reinterpret_cast<const __half2*>(&w0);
    float r0 = x0 - __low2float(h2);
    float r1 = x1 - __high2float(h2);
    w1 = packh2(r1, r0);
}

// ---------------- mma / ldmatrix / cp.async ----------------
__device__ __forceinline__ void mma_f16(float4& d, const uint32_t* a, const uint32_t* b) {
    asm volatile(
        "mma.sync.aligned.m16n8k16.row.col.f32.f16.f16.f32 "
        "{%0,%1,%2,%3}, {%4,%5,%6,%7}, {%8,%9}, {%0,%1,%2,%3};"
        : "+f"(d.x), "+f"(d.y), "+f"(d.z), "+f"(d.w)
        : "r"(a[0]), "r"(a[1]), "r"(a[2]), "r"(a[3]), "r"(b[0]), "r"(b[1]));
}
__device__ __forceinline__ void ldsm4(uint32_t& r0, uint32_t& r1, uint32_t& r2, uint32_t& r3,
                                      unsigned addr) {
    asm volatile("ldmatrix.sync.aligned.m8n8.x4.shared.b16 {%0,%1,%2,%3}, [%4];"
                 : "=r"(r0), "=r"(r1), "=r"(r2), "=r"(r3) : "r"(addr));
}
__device__ __forceinline__ void sts128(unsigned addr, uint32_t a, uint32_t b, uint32_t c, uint32_t d) {
    asm volatile("st.shared.v4.b32 [%0], {%1,%2,%3,%4};"
                 :: "r"(addr), "r"(a), "r"(b), "r"(c), "r"(d));
}
__device__ __forceinline__ void cpa16(unsigned dst, const void* src, unsigned srcsz) {
    asm volatile("cp.async.cg.shared.global [%0], [%1], 16, %2;"
                 :: "r"(dst), "l"(src), "r"(srcsz));
}
__device__ __forceinline__ void cpa_commit() {
    asm volatile("cp.async.commit_group;" ::: "memory");
}
__device__ __forceinline__ void cpa_wait0() {
    asm volatile("cp.async.wait_group 0;" ::: "memory");
}
__device__ __forceinline__ void cpa_wait1() {
    asm volatile("cp.async.wait_group 1;" ::: "memory");
}

// ---------------- one-time: split a matrix into 2 fp16 planes (optional scale) ----------------
__global__ void split_mat(const float* __restrict__ src, uint16_t* __restrict__ dst, long n2, float sc) {
    long i = (long)blockIdx.x * blockDim.x + threadIdx.x;
    if (i >= n2) return;
    float2 v = ((const float2*)src)[i];
    uint32_t w0, w1;
    split2(v.x * sc, v.y * sc, w0, w1);
    uint32_t* d = (uint32_t*)dst;
    d[i] = w0; d[i + n2] = w1;
}

// ---------------- one-time: W_b transpose + split (scaled) ----------------
__global__ void transpose_split_wb(const float* __restrict__ Wb) {
    __shared__ float t[32][33];
    int k0 = blockIdx.x * 32;
    int n0 = blockIdx.y * 32;
    for (int i = threadIdx.y; i < 32; i += 8)
        t[i][threadIdx.x] = Wb[(size_t)(k0 + i) * DHID + n0 + threadIdx.x];
    __syncthreads();
    const size_t PS = (size_t)DHID * DIMG;
    for (int i = threadIdx.y; i < 32; i += 8) {
        float v = t[threadIdx.x][i] * BSCALE;
        uint32_t w0, w1;
        split2(v, 0.f, w0, w1);
        size_t o = (size_t)(n0 + i) * DIMG + k0 + threadIdx.x;
        g_pWbT[o]      = (uint16_t)(w0 & 0xFFFF);
        g_pWbT[o + PS] = (uint16_t)(w1 & 0xFFFF);
    }
}

// ---------------- zero the one-hot output ----------------
__global__ void zero_out(float4* o, long long n4) {
    long long i = (long long)blockIdx.x * blockDim.x + threadIdx.x;
    if (i < n4) o[i] = make_float4(0.f, 0.f, 0.f, 0.f);
}

// =====================================================================
// fp16x2-split (3-product) tensor-core GEMM: C = (A[M,K]*B[N,K]^T)/BSCALE
// CTA tile 64x128, 256 threads, 8 warps (2x4), warp tile 32x32.
// K staged via cp.async, TRIPLE-buffered, wait_group 1 (latency hidden).
// 3 CTAs/SM. EPI=0: store fp32 C. EPI=1: +bias+gumbel+argmax (into amaxW).
// EPI=2: fp32 C + h planes.
// GATE: z==0 slice stages A on the fly from emb[token] (tokens decoded from
// amaxR in prologue; (x==0) CTA writes one-hot + g_tok for prevStep).
// =====================================================================
template<int EPI, bool NG, bool GATE>
__global__ __launch_bounds__(256, 3)
void bgemm(const uint16_t* __restrict__ A0, size_t sA0, const uint16_t* __restrict__ B0, size_t sB0,
           float* C0, int K0,
           const uint16_t* __restrict__ A1, size_t sA1, const uint16_t* __restrict__ B1, size_t sB1,
           float* C1, int K1,
           int Nn, const float* __restrict__ bout, const float* __restrict__ gumbel, int step,
           uint16_t* hpl,
           const float* __restrict__ emb, const unsigned long long* __restrict__ amaxR,
           int prevStep, float* __restrict__ onehot, unsigned long long* amaxW)
{
    const uint16_t* A; const uint16_t* B; float* C; int K; size_t sA, sB;
    if (blockIdx.z == 0) { A = A0; sA = sA0; B = B0; sB = sB0; C = C0; K = K0; }
    else                 { A = A1; sA = sA1; B = B1; sB = sB1; C = C1; K = K1; }

    extern __shared__ uint8_t dynraw[];
    unsigned dynb = (unsigned)__cvta_generic_to_shared(dynraw);
    dynb = (dynb + 127u) & ~127u;
    __shared__ unsigned long long rowmax[64];
    __shared__ int s_tok[64];

    const int tid  = threadIdx.x;
    const int lane = tid & 31;
    const int wid  = tid >> 5;
    const int wm = wid >> 2;          // 0..1
    const int wn = wid & 3;           // 0..3
    const int gid = lane >> 2;        // 0..7
    const int tig = lane & 3;         // 0..3
    const int bm = blockIdx.y * 64;
    const int bn = blockIdx.x * 128;

    const bool gateA = GATE && (blockIdx.z == 0);

    // ---- GATE prologue: decode tokens; single-writer one-hot + g_tok ----
    if (gateA) {
        if (tid < 64) {
            int t = BOS_TOK;
            if (prevStep >= 0)
                t = unpack_tok(amaxR[bm + tid]);
            s_tok[tid] = t;
            if (prevStep >= 0 && blockIdx.x == 0) {
                g_tok[prevStep * NB + bm + tid] = t;
                onehot[((size_t)(bm + tid) * NS + prevStep) * NV + t] = 1.0f;
            }
        }
        __syncthreads();
    }

    // ---- staging ids: A 64 rows x 4 chunks; B 128 rows x 4 chunks (2/thread) ----
    const int rowA = tid >> 2, chA = tid & 3;
    const int rowB = tid >> 1, chB2 = (tid & 1) * 2;
    const unsigned soffA = (unsigned)(rowA * 64 + ((chA ^ ((rowA >> 1) & 3)) << 4));
    const unsigned soffB0 = (unsigned)(rowB * 64 + (((chB2)     ^ ((rowB >> 1) & 3)) << 4));
    const unsigned soffB1 = (unsigned)(rowB * 64 + (((chB2 + 1) ^ ((rowB >> 1) & 3)) << 4));

    const uint16_t* Agp = A + (size_t)(bm + rowA) * K + chA * 8;
    const uint16_t* Bgp = B + (size_t)(bn + rowB) * K + chB2 * 8;
    const unsigned nsz = (!NG || (bn + rowB) < Nn) ? 16u : 0u;

    // ---- ldmatrix per-lane offsets (kstep 0); XOR 32 selects kstep 1 ----
    unsigned aOff[2], bOff[2];
    {
        const int ra = wm * 32 + (lane & 7) + ((lane >> 3) & 1) * 8;
        const int ca = (lane >> 4) & 1;
#pragma unroll
        for (int mf = 0; mf < 2; ++mf) {
            int r = ra + mf * 16;
            aOff[mf] = (unsigned)(r * 64 + ((ca ^ ((r >> 1) & 3)) << 4));
        }
        const int rb = wn * 32 + ((lane >> 4) & 1) * 8 + (lane & 7);
        const int cb = (lane >> 3) & 1;
#pragma unroll
        for (int nfp = 0; nfp < 2; ++nfp) {
            int r = rb + nfp * 16;
            bOff[nfp] = (unsigned)(r * 64 + ((cb ^ ((r >> 1) & 3)) << 4));
        }
    }

    float4 acc[2][4];
#pragma unroll
    for (int i = 0; i < 2; i++)
#pragma unroll
        for (int j = 0; j < 4; j++) acc[i][j] = make_float4(0.f, 0.f, 0.f, 0.f);

    // smem layout per stage (24576 B): A planes @ +0,+4096; B planes @ +8192,+16384
    auto STAGE = [&](int kt, int buf) {
        const unsigned base = dynb + (unsigned)buf * 24576u;
        if (gateA) {
            // stage A directly from emb[token] with relu + split (same math as old pX path)
            const float* ep = emb + (size_t)s_tok[rowA] * DEMB + kt * 32 + chA * 8;
            float4 e0 = *(const float4*)ep;
            float4 e1 = *(const float4*)(ep + 4);
            e0.x = fmaxf(e0.x, 0.f); e0.y = fmaxf(e0.y, 0.f);
            e0.z = fmaxf(e0.z, 0.f); e0.w = fmaxf(e0.w, 0.f);
            e1.x = fmaxf(e1.x, 0.f); e1.y = fmaxf(e1.y, 0.f);
            e1.z = fmaxf(e1.z, 0.f); e1.w = fmaxf(e1.w, 0.f);
            uint32_t p00, p10, p01, p11, p02, p12, p03, p13;
            split2(e0.x, e0.y, p00, p10);
            split2(e0.z, e0.w, p01, p11);
            split2(e1.x, e1.y, p02, p12);
            split2(e1.z, e1.w, p03, p13);
            sts128(base + soffA,         p00, p01, p02, p03);
            sts128(base + 4096u + soffA, p10, p11, p12, p13);
        } else {
            const uint16_t* ap = Agp + kt * 32;
#pragma unroll
            for (int p = 0; p < 2; ++p)
                cpa16(base + (unsigned)p * 4096u + soffA, ap + (size_t)p * sA, 16u);
        }
        const unsigned bb = base + 8192u;
        const uint16_t* bp = Bgp + kt * 32;
#pragma unroll
        for (int p = 0; p < 2; ++p) {
            cpa16(bb + (unsigned)p * 8192u + soffB0, bp + (size_t)p * sB,     nsz);
            cpa16(bb + (unsigned)p * 8192u + soffB1, bp + (size_t)p * sB + 8, nsz);
        }
        cpa_commit();
    };

    if (EPI == 1 && tid < 64) rowmax[tid] = 0ull;

    const int KT = K >> 5;
    // prologue: stages 0 and 1 in flight; guarantee stage 0 resident
    STAGE(0, 0);
    if (KT > 1) { STAGE(1, 1); cpa_wait1(); }
    else        { cpa_wait0(); }
    __syncthreads();

    int buf = 0;
    for (int kt = 0; kt < KT; ++kt) {
        const unsigned ab = dynb + (unsigned)buf * 24576u;
        const unsigned bb = ab + 8192u;
#pragma unroll
        for (int kstep = 0; kstep < 2; ++kstep) {
            const unsigned kx = (unsigned)kstep << 5;
            uint32_t aF[2][2][4];
#pragma unroll
            for (int p = 0; p < 2; ++p)
#pragma unroll
                for (int mf = 0; mf < 2; ++mf)
                    ldsm4(aF[p][mf][0], aF[p][mf][1], aF[p][mf][2], aF[p][mf][3],
                          ab + (unsigned)p * 4096u + (aOff[mf] ^ kx));

            uint32_t bF[4][2];
            auto LDB = [&](int p) {
#pragma unroll
                for (int nfp = 0; nfp < 2; ++nfp) {
                    uint32_t r0, r1, r2, r3;
                    ldsm4(r0, r1, r2, r3, bb + (unsigned)p * 8192u + (bOff[nfp] ^ kx));
                    bF[2 * nfp][0] = r0;     bF[2 * nfp][1] = r1;
                    bF[2 * nfp + 1][0] = r2; bF[2 * nfp + 1][1] = r3;
                }
            };
            auto PROD = [&](int ap) {
#pragma unroll
                for (int mf = 0; mf < 2; ++mf)
#pragma unroll
                    for (int nf = 0; nf < 4; ++nf)
                        mma_f16(acc[mf][nf], aF[ap][mf], bF[nf]);
            };
            // smallest terms first, a0*b0 last
            LDB(1); PROD(0);            // a0*b1
            LDB(0); PROD(1); PROD(0);   // a1*b0, a0*b0
        }

        // prefetch kt+2 into the third buffer
        if (kt + 2 < KT) {
            int buf2 = buf + 2; if (buf2 >= 3) buf2 -= 3;
            STAGE(kt + 2, buf2);
            cpa_wait1();                // stage kt+1 resident; kt+2 may be in flight
        } else {
            cpa_wait0();                // drain tail
        }
        __syncthreads();
        if (++buf == 3) buf = 0;
    }

    // undo B pre-scale
#pragma unroll
    for (int i = 0; i < 2; i++)
#pragma unroll
        for (int j = 0; j < 4; j++) {
            acc[i][j].x *= INVBSC; acc[i][j].y *= INVBSC;
            acc[i][j].z *= INVBSC; acc[i][j].w *= INVBSC;
        }

    if (EPI == 0 || EPI == 2) {
#pragma unroll
        for (int mf = 0; mf < 2; ++mf) {
            const int row = bm + wm * 32 + mf * 16 + gid;
#pragma unroll
            for (int nf = 0; nf < 4; ++nf) {
                const int col = bn + wn * 32 + nf * 8 + 2 * tig;
                float4 v = acc[mf][nf];
                *(float2*)(C + (size_t)row * Nn + col)       = make_float2(v.x, v.y);
                *(float2*)(C + (size_t)(row + 8) * Nn + col) = make_float2(v.z, v.w);
                if (EPI == 2) {
                    const long PSH = (long)NB * DHID / 2;
                    uint32_t* d = (uint32_t*)hpl;
                    uint32_t w0, w1;
                    split2(v.x, v.y, w0, w1);
                    long o = ((long)row * Nn + col) >> 1;
                    d[o] = w0; d[o + PSH] = w1;
                    split2(v.z, v.w, w0, w1);
                    o = ((long)(row + 8) * Nn + col) >> 1;
                    d[o] = w0; d[o + PSH] = w1;
                }
            }
        }
    } else {
        // fused +bias +gumbel + packed argmax
#pragma unroll
        for (int mf = 0; mf < 2; ++mf) {
            const int lm0 = wm * 32 + mf * 16 + gid;
            const int m0 = bm + lm0;
            unsigned long long best0 = 0ull, best1 = 0ull;
#pragma unroll
            for (int nf = 0; nf < 4; ++nf) {
                const int col = bn + wn * 32 + nf * 8 + 2 * tig;
                if (!NG || col < Nn) {      // Nn even, col even => pair fully valid
                    float2 bo = *(const float2*)(bout + col);
                    const float* g0 = gumbel + ((size_t)step * NB + m0) * (size_t)NV + col;
                    float2 ga = *(const float2*)g0;
                    float2 gb = *(const float2*)(g0 + (size_t)8 * NV);
                    float4 v = acc[mf][nf];
                    unsigned long long p;
                    p = packmax(v.x + bo.x + ga.x, col);     if (p > best0) best0 = p;
                    p = packmax(v.y + bo.y + ga.y, col + 1); if (p > best0) best0 = p;
                    p = packmax(v.z + bo.x + gb.x, col);     if (p > best1) best1 = p;
                    p = packmax(v.w + bo.y + gb.y, col + 1); if (p > best1) best1 = p;
                }
            }
            if (best0) atomicMax(&rowmax[lm0], best0);
            if (best1) atomicMax(&rowmax[lm0 + 8], best1);
        }
        __syncthreads();
        if (tid < 64 && rowmax[tid])
            atomicMax(&amaxW[bm + tid], rowmax[tid]);
    }
}

// ---------------- GRU elementwise: h_new (fp32 + fp16 planes) + amax parity zero ----------------
__global__ void gru_elem(const float* __restrict__ b_ih, const float* __restrict__ b_hh,
                         const float* __restrict__ hOld, float* __restrict__ hNew,
                         uint16_t* __restrict__ hpl, unsigned long long* __restrict__ amaxZ)
{
    if (threadIdx.x == 0) amaxZ[blockIdx.x] = 0ull;   // zero parity buffer for next logits

    int idx = blockIdx.x * blockDim.x + threadIdx.x;
    int m = idx >> 8;
    int j = (idx & 255) * 4;
    const float* G1 = g_G1 + (size_t)m * (3 * DHID);
    const float* G2 = g_G2 + (size_t)m * (3 * DHID);

    float4 ir = *(const float4*)(G1 + j);
    float4 iz = *(const float4*)(G1 + DHID + j);
    float4 in_ = *(const float4*)(G1 + 2 * DHID + j);
    float4 hr = *(const float4*)(G2 + j);
    float4 hz = *(const float4*)(G2 + DHID + j);
    float4 hn = *(const float4*)(G2 + 2 * DHID + j);
    float4 bir = *(const float4*)(b_ih + j);
    float4 biz = *(const float4*)(b_ih + DHID + j);
    float4 bin = *(const float4*)(b_ih + 2 * DHID + j);
    float4 bhr = *(const float4*)(b_hh + j);
    float4 bhz = *(const float4*)(b_hh + DHID + j);
    float4 bhn = *(const float4*)(b_hh + 2 * DHID + j);
    float4 ho = *(const float4*)(hOld + (size_t)m * DHID + j);

    float4 res;
#define GRU1(c) { \
        float r = 1.f / (1.f + expf(-((ir.c + bir.c) + (hr.c + bhr.c)))); \
        float z = 1.f / (1.f + expf(-((iz.c + biz.c) + (hz.c + bhz.c)))); \
        float n = tanhf((in_.c + bin.c) + r * (hn.c + bhn.c)); \
        res.c = (1.f - z) * n + z * ho.c; }
    GRU1(x) GRU1(y) GRU1(z) GRU1(w)
#undef GRU1
    *(float4*)(hNew + (size_t)m * DHID + j) = res;

    const long PSH = (long)NB * DHID / 2;
    uint32_t a0, a1, b0, b1;
    split2(res.x, res.y, a0, a1);
    split2(res.z, res.w, b0, b1);
    uint32_t* d = (uint32_t*)hpl;
    long o = ((long)m * DHID + j) >> 1;
    d[o] = a0;       d[o + 1] = b0;
    d[o + PSH] = a1; d[o + 1 + PSH] = b1;
}

// ---------------- final step: decode step-31 token, one-hot, msg_lens ----------------
__global__ void last_finalize(float* __restrict__ out, int out_size) {
    int b = blockIdx.x;
    if (threadIdx.x != 0) return;
    // parity of step NS-1 = (NS-1)&1
    unsigned long long p = g_amax[((NS - 1) & 1) * NB + b];
    int t = unpack_tok(p);
    g_tok[(NS - 1) * NB + b] = t;
    out[((size_t)b * NS + (NS - 1)) * NV + t] = 1.0f;
    int len = NS;
    for (int s = NS - 1; s >= 0; --s) {
        if (g_tok[s * NB + b] == EOS_TOK) { len = s + 1; break; }
    }
    if (out_size >= NB * NS * NV + NB)
        out[(size_t)NB * NS * NV + b] = (float)len;
}

// ---------------- launch ----------------
extern "C" void kernel_launch(void* const* d_in, const int* in_sizes, int n_in,
                              void* d_out, int out_size)
{
    const float* image = (const float*)d_in[0];
    const float* W_b   = (const float*)d_in[1];
    const float* emb   = (const float*)d_in[2];
    const float* w_ih  = (const float*)d_in[3];
    const float* w_hh  = (const float*)d_in[4];
    const float* b_ih  = (const float*)d_in[5];
    const float* b_hh  = (const float*)d_in[6];
    const float* W_out = (const float*)d_in[7];
    const float* b_out = (const float*)d_in[8];
    const float* gum   = (const float*)d_in[9];
    float* out = (float*)d_out;

    float *p_h0, *p_h1, *p_G1, *p_G2;
    unsigned long long* p_amax;
    uint16_t *pImg, *pWbT, *pWih, *pWhh, *pWout, *pHA, *pHB;
    cudaGetSymbolAddress((void**)&p_h0,  g_h0);
    cudaGetSymbolAddress((void**)&p_h1,  g_h1);
    cudaGetSymbolAddress((void**)&p_G1,  g_G1);
    cudaGetSymbolAddress((void**)&p_G2,  g_G2);
    cudaGetSymbolAddress((void**)&p_amax, g_amax);
    cudaGetSymbolAddress((void**)&pImg,  g_pImg);
    cudaGetSymbolAddress((void**)&pWbT,  g_pWbT);
    cudaGetSymbolAddress((void**)&pWih,  g_pWih);
    cudaGetSymbolAddress((void**)&pWhh,  g_pWhh);
    cudaGetSymbolAddress((void**)&pWout, g_pWout);
    cudaGetSymbolAddress((void**)&pHA,   g_pHA);
    cudaGetSymbolAddress((void**)&pHB,   g_pHB);

    const int SHB = 3 * 24576 + 128;   // triple-buffered stages + alignment pad
    cudaFuncSetAttribute(bgemm<0, false, true>,  cudaFuncAttributeMaxDynamicSharedMemorySize, SHB);
    cudaFuncSetAttribute(bgemm<1, true, false>,  cudaFuncAttributeMaxDynamicSharedMemorySize, SHB);
    cudaFuncSetAttribute(bgemm<2, false, false>, cudaFuncAttributeMaxDynamicSharedMemorySize, SHB);

    // zero the one-hot region
    long long n4 = (long long)NB * NS * NV / 4;
    zero_out<<<(unsigned)((n4 + 255) / 256), 256>>>((float4*)out, n4);

    // one-time: weight/activation pre-splits (weights scaled by BSCALE)
    transpose_split_wb<<<dim3(DIMG / 32, DHID / 32), dim3(32, 8)>>>(W_b);
    {
        long n2;
        n2 = (long)3 * DHID * DEMB / 2;
        split_mat<<<(unsigned)((n2 + 255) / 256), 256>>>(w_ih, pWih, n2, BSCALE);
        n2 = (long)3 * DHID * DHID / 2;
        split_mat<<<(unsigned)((n2 + 255) / 256), 256>>>(w_hh, pWhh, n2, BSCALE);
        n2 = (long)NV * DHID / 2;
        split_mat<<<(unsigned)((n2 + 255) / 256), 256>>>(W_out, pWout, n2, BSCALE);
        n2 = (long)NB * DIMG / 2;
        split_mat<<<(unsigned)((n2 + 255) / 256), 256>>>(image, pImg, n2, 1.0f);
    }

    const size_t sImg  = (size_t)NB * DIMG;
    const size_t sWbT  = (size_t)DHID * DIMG;
    const size_t sWih  = (size_t)3 * DHID * DEMB;
    const size_t sWhh  = (size_t)3 * DHID * DHID;
    const size_t sWout = (size_t)NV * DHID;
    const size_t sH    = (size_t)NB * DHID;

    // h0 = image @ W_b -> g_h0 fp32 + pHA planes
    bgemm<2, false, false><<<dim3(DHID / 128, NB / 64, 1), 256, SHB>>>(
        pImg, sImg, pWbT, sWbT, p_h0, DIMG,
        pImg, sImg, pWbT, sWbT, p_h0, DIMG,
        DHID, nullptr, nullptr, 0, pHA,
        nullptr, nullptr, 0, nullptr, nullptr);

    for (int s = 0; s < NS; ++s) {
        const float* hc = (s & 1) ? p_h1 : p_h0;
        float*       hn = (s & 1) ? p_h0 : p_h1;
        uint16_t* pHc = (s & 1) ? pHB : pHA;
        uint16_t* pHn = (s & 1) ? pHA : pHB;
        unsigned long long* amaxR = p_amax + (size_t)((s + 1) & 1) * NB;  // (s-1)&1 == (s+1)&1
        unsigned long long* amaxW = p_amax + (size_t)(s & 1) * NB;

        // gates: z=0 -> G1 = relu(emb[tok]) @ w_ih^T (K=512, token decode + one-hot fused);
        //        z=1 -> G2 = h @ w_hh^T (K=1024)
        bgemm<0, false, true><<<dim3(3 * DHID / 128, NB / 64, 2), 256, SHB>>>(
            (const uint16_t*)emb, 0, pWih, sWih, p_G1, DEMB,
            pHc, sH, pWhh, sWhh, p_G2, DHID,
            3 * DHID, nullptr, nullptr, 0, nullptr,
            emb, amaxR, s - 1, out, nullptr);
        // gru: h_new + planes; zeroes amax parity buffer for this step's logits
        gru_elem<<<(NB * DHID / 4) / 256, 256>>>(b_ih, b_hh, hc, hn, pHn, amaxW);
        // logits + bias + gumbel + argmax -> amaxW
        bgemm<1, true, false><<<dim3((NV + 127) / 128, NB / 64, 1), 256, SHB>>>(
            pHn, sH, pWout, sWout, nullptr, DHID,
            pHn, sH, pWout, sWout, nullptr, DHID,
            NV, b_out, gum, s, nullptr,
            nullptr, nullptr, 0, nullptr, amaxW);
    }

    last_finalize<<<NB, 32>>>(out, out_size);
}